// round 7
// baseline (speedup 1.0000x reference)
#include <cuda_runtime.h>
#include <math.h>
#include <stdint.h>

#define NN 50000
#define EE 400000
#define DD 128
#define HH 8
#define CC 16
#define EH 64
#define LL 6

static_assert(EE % 128 == 0, "edge tiling");
static_assert(NN % 8 == 0, "node tiling");

// ---------------- device scratch (static; no allocations allowed) ----------------
__device__ __align__(16) float g_h  [NN * DD];   // node features
__device__ __align__(16) float g_xl [NN * DD];   // lin_l output
__device__ __align__(16) float g_xr [NN * DD];   // lin_r output
__device__ __align__(16) float g_ef [EE * EH];   // encoded edge features
__device__             float g_a   [EE * HH];    // exp(logit), indexed by CSR SLOT
// CSR by destination node (built once per launch)
__device__ int  g_cnt   [NN];
__device__ int  g_wptr  [NN];
__device__ int  g_rowptr[NN + 1];
__device__ int2 g_csr    [EE];   // (orig edge id, src node) per slot
__device__ int  g_csr_dst[EE];   // dst node per slot

typedef unsigned long long u64;

__device__ __forceinline__ float warp_sum(float v) {
#pragma unroll
    for (int o = 16; o; o >>= 1) v += __shfl_xor_sync(0xffffffffu, v, o);
    return v;
}
// ---- packed f32x2 helpers (sm_100a) ----
__device__ __forceinline__ u64 dup2(float v) {
    u64 r; asm("mov.b64 %0, {%1, %1};" : "=l"(r) : "f"(v)); return r;
}
__device__ __forceinline__ u64 ffma2(u64 a, u64 b, u64 c) {
    u64 d; asm("fma.rn.f32x2 %0, %1, %2, %3;" : "=l"(d) : "l"(a), "l"(b), "l"(c));
    return d;
}
__device__ __forceinline__ float2 unpack2(u64 p) {
    float2 r; asm("mov.b64 {%0, %1}, %2;" : "=f"(r.x), "=f"(r.y) : "l"(p));
    return r;
}
__device__ __forceinline__ uint32_t to_tf32(float f) {
    uint32_t t; asm("cvt.rna.tf32.f32 %0, %1;" : "=r"(t) : "f"(f)); return t;
}

// ---------------- node encoder: x(N,9) -> LN -> relu -> g_h(N,128). 1 warp/node ----
__global__ void node_enc_kernel(const float* __restrict__ x,
                                const float* __restrict__ W,
                                const float* __restrict__ b,
                                const float* __restrict__ g,
                                const float* __restrict__ beta) {
    int warp = (blockIdx.x * blockDim.x + threadIdx.x) >> 5;
    int lane = threadIdx.x & 31;
    if (warp >= NN) return;
    float acc[4];
#pragma unroll
    for (int j = 0; j < 4; j++) acc[j] = b[lane + 32 * j];
#pragma unroll
    for (int k = 0; k < 9; k++) {
        float xv = x[warp * 9 + k];
#pragma unroll
        for (int j = 0; j < 4; j++) acc[j] += xv * W[k * DD + lane + 32 * j];
    }
    float s = 0.f;
#pragma unroll
    for (int j = 0; j < 4; j++) s += acc[j];
    float m = warp_sum(s) * (1.0f / DD);
    float v = 0.f;
#pragma unroll
    for (int j = 0; j < 4; j++) { float d = acc[j] - m; v += d * d; }
    v = warp_sum(v) * (1.0f / DD);
    float rstd = rsqrtf(v + 1e-5f);
#pragma unroll
    for (int j = 0; j < 4; j++) {
        int d = lane + 32 * j;
        float y = (acc[j] - m) * rstd * g[d] + beta[d];
        g_h[warp * DD + d] = fmaxf(y, 0.0f);
    }
}

// ---------------- edge encoder: edge_attr(E,3) -> LN -> relu -> g_ef(E,64) ---------
__global__ void edge_enc_kernel(const float* __restrict__ ea,
                                const float* __restrict__ W,
                                const float* __restrict__ b,
                                const float* __restrict__ g,
                                const float* __restrict__ beta) {
    int warp = (blockIdx.x * blockDim.x + threadIdx.x) >> 5;
    int lane = threadIdx.x & 31;
    if (warp >= EE) return;
    float a0 = b[lane], a1 = b[lane + 32];
#pragma unroll
    for (int k = 0; k < 3; k++) {
        float xv = ea[warp * 3 + k];
        a0 += xv * W[k * EH + lane];
        a1 += xv * W[k * EH + 32 + lane];
    }
    float m = warp_sum(a0 + a1) * (1.0f / EH);
    float d0 = a0 - m, d1 = a1 - m;
    float v = warp_sum(d0 * d0 + d1 * d1) * (1.0f / EH);
    float rstd = rsqrtf(v + 1e-5f);
    float y0 = d0 * rstd * g[lane] + beta[lane];
    float y1 = d1 * rstd * g[lane + 32] + beta[lane + 32];
    g_ef[warp * EH + lane]      = fmaxf(y0, 0.f);
    g_ef[warp * EH + 32 + lane] = fmaxf(y1, 0.f);
}

// ---------------- CSR build (once per launch) --------------------------------------
__global__ void csr_zero_kernel() {
    int i = blockIdx.x * blockDim.x + threadIdx.x;
    if (i < NN) g_cnt[i] = 0;
}
__global__ void csr_count_kernel(const int* __restrict__ ei) {
    int e = blockIdx.x * blockDim.x + threadIdx.x;
    if (e < EE) atomicAdd(&g_cnt[ei[EE + e]], 1);
}
__global__ void csr_scan_kernel() {
    __shared__ int warpsum[32];
    __shared__ int s_total;
    int tid = threadIdx.x, lane = tid & 31, wid = tid >> 5;
    if (tid == 0) { s_total = 0; g_rowptr[0] = 0; }
    __syncthreads();
    for (int base = 0; base < NN; base += 1024) {
        int i = base + tid;
        int v = (i < NN) ? g_cnt[i] : 0;
        int x = v;
#pragma unroll
        for (int o = 1; o < 32; o <<= 1) {
            int t = __shfl_up_sync(0xffffffffu, x, o);
            if (lane >= o) x += t;
        }
        if (lane == 31) warpsum[wid] = x;
        __syncthreads();
        if (wid == 0) {
            int w = warpsum[lane];
#pragma unroll
            for (int o = 1; o < 32; o <<= 1) {
                int t = __shfl_up_sync(0xffffffffu, w, o);
                if (lane >= o) w += t;
            }
            warpsum[lane] = w;
        }
        __syncthreads();
        int incl = s_total + (wid ? warpsum[wid - 1] : 0) + x;
        if (i < NN) {
            g_rowptr[i + 1] = incl;
            g_wptr[i] = incl - v;
        }
        __syncthreads();
        if (tid == 0) s_total += warpsum[31];
        __syncthreads();
    }
}
__global__ void csr_scatter_kernel(const int* __restrict__ ei) {
    int e = blockIdx.x * blockDim.x + threadIdx.x;
    if (e < EE) {
        int d = ei[EE + e];
        int pos = atomicAdd(&g_wptr[d], 1);
        g_csr[pos] = make_int2(e, ei[e]);
        g_csr_dst[pos] = d;
    }
}

// ---------------- xl/xr GEMM: 128x128 tile, 8x8/thread, FFMA2 inner loop -----------
#define TM 128
#define TN 128
#define TK 16
#define LIN_SMEM (2 * TK * TM * 8 + 2 * TK * TN * 4)
__global__ __launch_bounds__(256, 2) void lin_kernel(
    const float* __restrict__ Wl, const float* __restrict__ bl,
    const float* __restrict__ Wr, const float* __restrict__ br) {
    extern __shared__ char smem_raw[];
    u64*   sA2 = (u64*)smem_raw;                         // [2][TK][TM] dup pairs
    float* sB  = (float*)(smem_raw + 2 * TK * TM * 8);   // [2][TK][TN]
    const float* W  = blockIdx.y ? Wr : Wl;
    const float* bv = blockIdx.y ? br : bl;
    float* dst = blockIdx.y ? g_xr : g_xl;
    int m0 = blockIdx.x * TM;
    int tid = threadIdx.x;
    int tn = tid & 15, tm = tid >> 4;

    u64 acc[8][4];
#pragma unroll
    for (int i = 0; i < 8; i++)
#pragma unroll
        for (int j = 0; j < 4; j++) acc[i][j] = 0ull;

    float4 ra[2], rb[2];

#define LDG_AB(kc)                                                              \
    {                                                                           \
        _Pragma("unroll")                                                       \
        for (int r = 0; r < 2; r++) {                                           \
            int idx = tid + r * 256;                                            \
            int m = idx >> 2, kq = (idx & 3) << 2;                              \
            int gm = m0 + m;                                                    \
            ra[r] = make_float4(0.f, 0.f, 0.f, 0.f);                            \
            if (gm < NN)                                                        \
                ra[r] = *(const float4*)&g_h[gm * DD + (kc) * TK + kq];         \
            int k = idx >> 5, nq = (idx & 31) << 2;                             \
            rb[r] = *(const float4*)&W[((kc) * TK + k) * DD + nq];              \
        }                                                                       \
    }
#define STS_AB(buf)                                                             \
    {                                                                           \
        _Pragma("unroll")                                                       \
        for (int r = 0; r < 2; r++) {                                           \
            int idx = tid + r * 256;                                            \
            int m = idx >> 2, kq = (idx & 3) << 2;                              \
            u64* pa = sA2 + (buf) * TK * TM;                                    \
            pa[(kq + 0) * TM + m] = dup2(ra[r].x);                              \
            pa[(kq + 1) * TM + m] = dup2(ra[r].y);                              \
            pa[(kq + 2) * TM + m] = dup2(ra[r].z);                              \
            pa[(kq + 3) * TM + m] = dup2(ra[r].w);                              \
            int k = idx >> 5, nq = (idx & 31) << 2;                             \
            *(float4*)&sB[((buf) * TK + k) * TN + nq] = rb[r];                  \
        }                                                                       \
    }

    LDG_AB(0);
    STS_AB(0);
    __syncthreads();
#pragma unroll
    for (int kc = 0; kc < DD / TK; kc++) {
        int buf = kc & 1;
        if (kc + 1 < DD / TK) LDG_AB(kc + 1);
#pragma unroll
        for (int kk = 0; kk < TK; kk++) {
            const u64* pa = sA2 + (buf * TK + kk) * TM + tm * 8;
            const u64* pb = (const u64*)&sB[(buf * TK + kk) * TN];
            u64 ap[8], bp[4];
#pragma unroll
            for (int i = 0; i < 8; i++) ap[i] = pa[i];
            bp[0] = pb[tn * 2];
            bp[1] = pb[tn * 2 + 1];
            bp[2] = pb[32 + tn * 2];
            bp[3] = pb[32 + tn * 2 + 1];
#pragma unroll
            for (int i = 0; i < 8; i++)
#pragma unroll
                for (int j = 0; j < 4; j++)
                    acc[i][j] = ffma2(ap[i], bp[j], acc[i][j]);
        }
        if (kc + 1 < DD / TK) {
            __syncthreads();
            STS_AB(buf ^ 1);
            __syncthreads();
        }
    }
    // epilogue
    float4 bias0 = *(const float4*)&bv[tn * 4];
    float4 bias1 = *(const float4*)&bv[64 + tn * 4];
#pragma unroll
    for (int i = 0; i < 8; i++) {
        int gm = m0 + tm * 8 + i;
        if (gm < NN) {
            float2 c0 = unpack2(acc[i][0]);
            float2 c1 = unpack2(acc[i][1]);
            float2 c2 = unpack2(acc[i][2]);
            float2 c3 = unpack2(acc[i][3]);
            float4 o0 = make_float4(c0.x + bias0.x, c0.y + bias0.y,
                                    c1.x + bias0.z, c1.y + bias0.w);
            float4 o1 = make_float4(c2.x + bias1.x, c2.y + bias1.y,
                                    c3.x + bias1.z, c3.y + bias1.w);
            *(float4*)&dst[gm * DD + tn * 4] = o0;
            *(float4*)&dst[gm * DD + 64 + tn * 4] = o1;
        }
    }
#undef LDG_AB
#undef STS_AB
}

// ---------------- pass A: persistent tf32 TC ee GEMM + logits + exp ----------------
// 592 persistent blocks; each loops over edge tiles. We/att staged ONCE per block;
// per tile only the 128-edge ef slab + src/dst are staged.
#define PA_EDGES 128
#define PA_GRID 592
#define EFS 68   // padded k-stride (bank-conflict-free fragment loads)
#define PASSA_SMEM (PA_EDGES * EFS * 4 + DD * EFS * 4 + DD * 4)
__global__ __launch_bounds__(256, 3) void passA_kernel(const float* __restrict__ We,
                                                       const float* __restrict__ att) {
    extern __shared__ char smem_raw[];
    uint32_t* sEf  = (uint32_t*)smem_raw;                          // [128][EFS] tf32
    uint32_t* sWeT = (uint32_t*)(smem_raw + PA_EDGES * EFS * 4);   // [128 n][EFS k]
    float*    sAtt = (float*)   (smem_raw + PA_EDGES * EFS * 4 + DD * EFS * 4);
    __shared__ int sSrc[PA_EDGES], sDst[PA_EDGES];
    int tid = threadIdx.x;
    int lane = tid & 31, wm = tid >> 5;
    int gid = lane >> 2, q = lane & 3;

    // stage We transposed (k-major -> [n][k]) as tf32 -- ONCE
    for (int idx = tid; idx < EH * DD; idx += 256) {
        int k = idx >> 7, n = idx & 127;
        sWeT[n * EFS + k] = to_tf32(We[idx]);
    }
    if (tid < DD) sAtt[tid] = att[tid];

    int r0 = wm * 16 + gid;
    int r1 = r0 + 8;
    const uint32_t* efr0 = sEf + r0 * EFS;
    const uint32_t* efr1 = sEf + r1 * EFS;

    for (int tile = blockIdx.x; tile < EE / PA_EDGES; tile += PA_GRID) {
        int eb = tile * PA_EDGES;
        __syncthreads();   // previous iteration's readers done before restaging
        if (tid < PA_EDGES) {
            int2 c = g_csr[eb + tid];
            sSrc[tid] = c.y;
            sDst[tid] = g_csr_dst[eb + tid];
        }
        for (int idx = tid; idx < PA_EDGES * (EH / 4); idx += 256) {
            int r = idx >> 4, c4 = (idx & 15) << 2;
            int e = g_csr[eb + r].x;
            float4 v = *(const float4*)&g_ef[(size_t)e * EH + c4];
            uint4 t;
            t.x = to_tf32(v.x); t.y = to_tf32(v.y);
            t.z = to_tf32(v.z); t.w = to_tf32(v.w);
            *(uint4*)&sEf[r * EFS + c4] = t;
        }
        __syncthreads();

        const float* xl0 = g_xl + (size_t)sSrc[r0] * DD;
        const float* xr0 = g_xr + (size_t)sDst[r0] * DD;
        const float* xl1 = g_xl + (size_t)sSrc[r1] * DD;
        const float* xr1 = g_xr + (size_t)sDst[r1] * DD;

        float h0[8], h1[8];
#pragma unroll
        for (int h = 0; h < 8; h++) { h0[h] = 0.f; h1[h] = 0.f; }

#pragma unroll
        for (int half = 0; half < 2; half++) {
            float d[8][4];
#pragma unroll
            for (int n8 = 0; n8 < 8; n8++)
#pragma unroll
                for (int j = 0; j < 4; j++) d[n8][j] = 0.f;

#pragma unroll
            for (int k0 = 0; k0 < 8; k0++) {
                uint32_t a0 = efr0[k0 * 8 + q];
                uint32_t a1 = efr1[k0 * 8 + q];
                uint32_t a2 = efr0[k0 * 8 + q + 4];
                uint32_t a3 = efr1[k0 * 8 + q + 4];
#pragma unroll
                for (int n8 = 0; n8 < 8; n8++) {
                    int n = half * 8 + n8;
                    uint32_t b0 = sWeT[(n * 8 + gid) * EFS + k0 * 8 + q];
                    uint32_t b1 = sWeT[(n * 8 + gid) * EFS + k0 * 8 + q + 4];
                    asm volatile(
                        "mma.sync.aligned.m16n8k8.row.col.f32.tf32.tf32.f32 "
                        "{%0,%1,%2,%3}, {%4,%5,%6,%7}, {%8,%9}, {%0,%1,%2,%3};"
                        : "+f"(d[n8][0]), "+f"(d[n8][1]), "+f"(d[n8][2]), "+f"(d[n8][3])
                        : "r"(a0), "r"(a1), "r"(a2), "r"(a3), "r"(b0), "r"(b1));
                }
            }
#pragma unroll
            for (int n8 = 0; n8 < 8; n8++) {
                int n = half * 8 + n8;
                int c = n * 8 + q * 2;
                float2 av  = *(const float2*)&sAtt[c];
                float2 l0v = *(const float2*)&xl0[c];
                float2 r0v = *(const float2*)&xr0[c];
                float2 l1v = *(const float2*)&xl1[c];
                float2 r1v = *(const float2*)&xr1[c];
                float v00 = d[n8][0] + l0v.x + r0v.x; v00 = v00 > 0.f ? v00 : 0.2f * v00;
                float v01 = d[n8][1] + l0v.y + r0v.y; v01 = v01 > 0.f ? v01 : 0.2f * v01;
                float v10 = d[n8][2] + l1v.x + r1v.x; v10 = v10 > 0.f ? v10 : 0.2f * v10;
                float v11 = d[n8][3] + l1v.y + r1v.y; v11 = v11 > 0.f ? v11 : 0.2f * v11;
                h0[n >> 1] += v00 * av.x + v01 * av.y;
                h1[n >> 1] += v10 * av.x + v11 * av.y;
            }
        }
#pragma unroll
        for (int h = 0; h < 8; h++) {
            h0[h] += __shfl_xor_sync(0xffffffffu, h0[h], 1);
            h0[h] += __shfl_xor_sync(0xffffffffu, h0[h], 2);
            h1[h] += __shfl_xor_sync(0xffffffffu, h1[h], 1);
            h1[h] += __shfl_xor_sync(0xffffffffu, h1[h], 2);
        }
        size_t p0 = (size_t)(eb + r0) * HH;
        size_t p1 = (size_t)(eb + r1) * HH;
        g_a[p0 + 2 * q]     = expf(h0[2 * q]);
        g_a[p0 + 2 * q + 1] = expf(h0[2 * q + 1]);
        g_a[p1 + 2 * q]     = expf(h1[2 * q]);
        g_a[p1 + 2 * q + 1] = expf(h1[2 * q + 1]);
    }
}

// ---------------- pass B: per-dst gather (no atomics) + fused residual+LN+relu -----
__global__ void passB_kernel(const float* __restrict__ cb,
                             const float* __restrict__ g,
                             const float* __restrict__ beta) {
    int node = (blockIdx.x * blockDim.x + threadIdx.x) >> 5;
    int lane = threadIdx.x & 31;
    if (node >= NN) return;
    int start = g_rowptr[node], end = g_rowptr[node + 1];

    // denominator: sum over in-edge slots per head (coalesced: 4 slots x 8 heads)
    float s = 0.f;
    for (int p0 = start; p0 < end; p0 += 4) {
        int p = p0 + (lane >> 3);
        if (p < end) s += g_a[(size_t)p * HH + (lane & 7)];
    }
    s += __shfl_xor_sync(0xffffffffu, s, 8);
    s += __shfl_xor_sync(0xffffffffu, s, 16);
    float sh = __shfl_sync(0xffffffffu, s, lane >> 2);
    float rinv = 1.0f / (sh + 1e-16f);

    // weighted aggregation of xl[src], 4-way unrolled for MLP
    int head = lane >> 2;
    float4 acc = make_float4(0.f, 0.f, 0.f, 0.f);
    int p = start;
    for (; p + 4 <= end; p += 4) {
        int s0 = g_csr[p].y,     s1 = g_csr[p + 1].y;
        int s2 = g_csr[p + 2].y, s3 = g_csr[p + 3].y;
        float a0 = g_a[(size_t)(p)     * HH + head];
        float a1 = g_a[(size_t)(p + 1) * HH + head];
        float a2 = g_a[(size_t)(p + 2) * HH + head];
        float a3 = g_a[(size_t)(p + 3) * HH + head];
        float4 x0 = *(const float4*)&g_xl[(size_t)s0 * DD + 4 * lane];
        float4 x1 = *(const float4*)&g_xl[(size_t)s1 * DD + 4 * lane];
        float4 x2 = *(const float4*)&g_xl[(size_t)s2 * DD + 4 * lane];
        float4 x3 = *(const float4*)&g_xl[(size_t)s3 * DD + 4 * lane];
        acc.x += a0 * x0.x + a1 * x1.x + a2 * x2.x + a3 * x3.x;
        acc.y += a0 * x0.y + a1 * x1.y + a2 * x2.y + a3 * x3.y;
        acc.z += a0 * x0.z + a1 * x1.z + a2 * x2.z + a3 * x3.z;
        acc.w += a0 * x0.w + a1 * x1.w + a2 * x2.w + a3 * x3.w;
    }
    for (; p < end; p++) {
        int sn = g_csr[p].y;
        float al = g_a[(size_t)p * HH + head];
        float4 xv = *(const float4*)&g_xl[(size_t)sn * DD + 4 * lane];
        acc.x += al * xv.x; acc.y += al * xv.y;
        acc.z += al * xv.z; acc.w += al * xv.w;
    }
    acc.x *= rinv; acc.y *= rinv; acc.z *= rinv; acc.w *= rinv;

    // residual + conv bias, then LN + relu, write back to g_h
    int d0 = 4 * lane;
    float4 hv = *(const float4*)&g_h[node * DD + d0];
    float4 cv = *(const float4*)&cb[d0];
    float a0 = acc.x + cv.x + hv.x;
    float a1 = acc.y + cv.y + hv.y;
    float a2 = acc.z + cv.z + hv.z;
    float a3 = acc.w + cv.w + hv.w;
    float m = warp_sum(a0 + a1 + a2 + a3) * (1.0f / DD);
    float e0d = a0 - m, e1d = a1 - m, e2d = a2 - m, e3d = a3 - m;
    float v = warp_sum(e0d * e0d + e1d * e1d + e2d * e2d + e3d * e3d) * (1.0f / DD);
    float rstd = rsqrtf(v + 1e-5f);
    float4 gv = *(const float4*)&g[d0];
    float4 bv = *(const float4*)&beta[d0];
    float4 o;
    o.x = fmaxf(e0d * rstd * gv.x + bv.x, 0.f);
    o.y = fmaxf(e1d * rstd * gv.y + bv.y, 0.f);
    o.z = fmaxf(e2d * rstd * gv.z + bv.z, 0.f);
    o.w = fmaxf(e3d * rstd * gv.w + bv.w, 0.f);
    *(float4*)&g_h[node * DD + d0] = o;
}

// ---------------- head: relu(h@W1+b1) @ W2 -> sigmoid. 1 warp/node -----------------
__global__ void head_kernel(float* __restrict__ out,
                            const float* __restrict__ W1, const float* __restrict__ b1,
                            const float* __restrict__ W2, const float* __restrict__ b2) {
    int warp = (blockIdx.x * blockDim.x + threadIdx.x) >> 5;
    int lane = threadIdx.x & 31;
    if (warp >= NN) return;
    float hr[4];
#pragma unroll
    for (int q = 0; q < 4; q++) hr[q] = g_h[warp * DD + q * 32 + lane];
    float z0 = b1[lane], z1 = b1[lane + 32];
#pragma unroll
    for (int q = 0; q < 4; q++) {
#pragma unroll 8
        for (int kk = 0; kk < 32; kk++) {
            float hk = __shfl_sync(0xffffffffu, hr[q], kk);
            int k = q * 32 + kk;
            z0 += hk * W1[k * 64 + lane];
            z1 += hk * W1[k * 64 + 32 + lane];
        }
    }
    z0 = fmaxf(z0, 0.f);
    z1 = fmaxf(z1, 0.f);
    float p = z0 * W2[lane] + z1 * W2[lane + 32];
    p = warp_sum(p);
    if (lane == 0) out[warp] = 1.0f / (1.0f + expf(-(p + b2[0])));
}

// ---------------- launch ----------------------------------------------------------
extern "C" void kernel_launch(void* const* d_in, const int* in_sizes, int n_in,
                              void* d_out, int out_size) {
    const float* x    = (const float*)d_in[0];
    const int*   ei   = (const int*)  d_in[1];
    const float* ea   = (const float*)d_in[2];
    const float* neW  = (const float*)d_in[3];
    const float* neb  = (const float*)d_in[4];
    const float* neg  = (const float*)d_in[5];
    const float* nebt = (const float*)d_in[6];
    const float* eeW  = (const float*)d_in[7];
    const float* eeb  = (const float*)d_in[8];
    const float* eeg  = (const float*)d_in[9];
    const float* eebt = (const float*)d_in[10];
    const float* Wl   = (const float*)d_in[11];
    const float* bl   = (const float*)d_in[12];
    const float* Wr   = (const float*)d_in[13];
    const float* br   = (const float*)d_in[14];
    const float* We   = (const float*)d_in[15];
    const float* att  = (const float*)d_in[16];
    const float* cb   = (const float*)d_in[17];
    const float* lng  = (const float*)d_in[18];
    const float* lnb  = (const float*)d_in[19];
    const float* W1   = (const float*)d_in[20];
    const float* b1   = (const float*)d_in[21];
    const float* W2   = (const float*)d_in[22];
    const float* b2   = (const float*)d_in[23];
    float* out = (float*)d_out;

    cudaFuncSetAttribute(lin_kernel, cudaFuncAttributeMaxDynamicSharedMemorySize,
                         LIN_SMEM);
    cudaFuncSetAttribute(passA_kernel, cudaFuncAttributeMaxDynamicSharedMemorySize,
                         PASSA_SMEM);

    dim3 lin_grid((NN + TM - 1) / TM, 2);

    // index 3 = lin_kernel so ncu profiles the FFMA2 GEMM this round
    node_enc_kernel<<<NN / 8, 256>>>(x, neW, neb, neg, nebt);                    // 0
    csr_zero_kernel<<<(NN + 255) / 256, 256>>>();                                // 1
    csr_count_kernel<<<(EE + 255) / 256, 256>>>(ei);                             // 2
    lin_kernel<<<lin_grid, 256, LIN_SMEM>>>(Wl, bl, Wr, br);                     // 3
    csr_scan_kernel<<<1, 1024>>>();                                              // 4
    csr_scatter_kernel<<<(EE + 255) / 256, 256>>>(ei);                           // 5
    edge_enc_kernel<<<EE / 8, 256>>>(ea, eeW, eeb, eeg, eebt);                   // 6

    for (int l = 0; l < LL; l++) {
        if (l > 0)
            lin_kernel<<<lin_grid, 256, LIN_SMEM>>>(Wl + l * DD * DD, bl + l * DD,
                                                    Wr + l * DD * DD, br + l * DD);
        passA_kernel<<<PA_GRID, 256, PASSA_SMEM>>>(We + l * EH * DD,
                                                   att + l * HH * CC);
        passB_kernel<<<(NN * 32 + 255) / 256, 256>>>(cb + l * DD, lng + l * DD,
                                                     lnb + l * DD);
    }
    head_kernel<<<NN / 8, 256>>>(out, W1, b1, W2, b2);
}

// round 8
// speedup vs baseline: 1.0077x; 1.0077x over previous
#include <cuda_runtime.h>
#include <math.h>
#include <stdint.h>

#define NN 50000
#define EE 400000
#define DD 128
#define HH 8
#define CC 16
#define EH 64
#define LL 6

static_assert(EE % 128 == 0, "edge tiling");
static_assert(NN % 8 == 0, "node tiling");

// ---------------- device scratch (static; no allocations allowed) ----------------
__device__ __align__(16) float g_h  [NN * DD];   // node features
__device__ __align__(16) float g_xl [NN * DD];   // lin_l output
__device__ __align__(16) float g_xr [NN * DD];   // lin_r output
__device__ __align__(16) float g_ef [EE * EH];   // encoded edge features
__device__             float g_a   [EE * HH];    // exp(logit), indexed by CSR SLOT
// CSR by destination node (built once per launch)
__device__ int  g_cnt   [NN];
__device__ int  g_wptr  [NN];
__device__ int  g_rowptr[NN + 1];
__device__ int2 g_csr    [EE];   // (orig edge id, src node) per slot
__device__ int  g_csr_dst[EE];   // dst node per slot

typedef unsigned long long u64;

__device__ __forceinline__ float warp_sum(float v) {
#pragma unroll
    for (int o = 16; o; o >>= 1) v += __shfl_xor_sync(0xffffffffu, v, o);
    return v;
}
// ---- packed f32x2 helpers (sm_100a) ----
__device__ __forceinline__ u64 dup2(float v) {
    u64 r; asm("mov.b64 %0, {%1, %1};" : "=l"(r) : "f"(v)); return r;
}
__device__ __forceinline__ u64 ffma2(u64 a, u64 b, u64 c) {
    u64 d; asm("fma.rn.f32x2 %0, %1, %2, %3;" : "=l"(d) : "l"(a), "l"(b), "l"(c));
    return d;
}
__device__ __forceinline__ float2 unpack2(u64 p) {
    float2 r; asm("mov.b64 {%0, %1}, %2;" : "=f"(r.x), "=f"(r.y) : "l"(p));
    return r;
}
__device__ __forceinline__ uint32_t to_tf32(float f) {
    uint32_t t; asm("cvt.rna.tf32.f32 %0, %1;" : "=r"(t) : "f"(f)); return t;
}

// ---------------- node encoder: x(N,9) -> LN -> relu -> g_h(N,128). 1 warp/node ----
__global__ void node_enc_kernel(const float* __restrict__ x,
                                const float* __restrict__ W,
                                const float* __restrict__ b,
                                const float* __restrict__ g,
                                const float* __restrict__ beta) {
    int warp = (blockIdx.x * blockDim.x + threadIdx.x) >> 5;
    int lane = threadIdx.x & 31;
    if (warp >= NN) return;
    float acc[4];
#pragma unroll
    for (int j = 0; j < 4; j++) acc[j] = b[lane + 32 * j];
#pragma unroll
    for (int k = 0; k < 9; k++) {
        float xv = x[warp * 9 + k];
#pragma unroll
        for (int j = 0; j < 4; j++) acc[j] += xv * W[k * DD + lane + 32 * j];
    }
    float s = 0.f;
#pragma unroll
    for (int j = 0; j < 4; j++) s += acc[j];
    float m = warp_sum(s) * (1.0f / DD);
    float v = 0.f;
#pragma unroll
    for (int j = 0; j < 4; j++) { float d = acc[j] - m; v += d * d; }
    v = warp_sum(v) * (1.0f / DD);
    float rstd = rsqrtf(v + 1e-5f);
#pragma unroll
    for (int j = 0; j < 4; j++) {
        int d = lane + 32 * j;
        float y = (acc[j] - m) * rstd * g[d] + beta[d];
        g_h[warp * DD + d] = fmaxf(y, 0.0f);
    }
}

// ---------------- edge encoder: edge_attr(E,3) -> LN -> relu -> g_ef(E,64) ---------
__global__ void edge_enc_kernel(const float* __restrict__ ea,
                                const float* __restrict__ W,
                                const float* __restrict__ b,
                                const float* __restrict__ g,
                                const float* __restrict__ beta) {
    int warp = (blockIdx.x * blockDim.x + threadIdx.x) >> 5;
    int lane = threadIdx.x & 31;
    if (warp >= EE) return;
    float a0 = b[lane], a1 = b[lane + 32];
#pragma unroll
    for (int k = 0; k < 3; k++) {
        float xv = ea[warp * 3 + k];
        a0 += xv * W[k * EH + lane];
        a1 += xv * W[k * EH + 32 + lane];
    }
    float m = warp_sum(a0 + a1) * (1.0f / EH);
    float d0 = a0 - m, d1 = a1 - m;
    float v = warp_sum(d0 * d0 + d1 * d1) * (1.0f / EH);
    float rstd = rsqrtf(v + 1e-5f);
    float y0 = d0 * rstd * g[lane] + beta[lane];
    float y1 = d1 * rstd * g[lane + 32] + beta[lane + 32];
    g_ef[warp * EH + lane]      = fmaxf(y0, 0.f);
    g_ef[warp * EH + 32 + lane] = fmaxf(y1, 0.f);
}

// ---------------- CSR build (once per launch) --------------------------------------
__global__ void csr_zero_kernel() {
    int i = blockIdx.x * blockDim.x + threadIdx.x;
    if (i < NN) g_cnt[i] = 0;
}
__global__ void csr_count_kernel(const int* __restrict__ ei) {
    int e = blockIdx.x * blockDim.x + threadIdx.x;
    if (e < EE) atomicAdd(&g_cnt[ei[EE + e]], 1);
}
__global__ void csr_scan_kernel() {
    __shared__ int warpsum[32];
    __shared__ int s_total;
    int tid = threadIdx.x, lane = tid & 31, wid = tid >> 5;
    if (tid == 0) { s_total = 0; g_rowptr[0] = 0; }
    __syncthreads();
    for (int base = 0; base < NN; base += 1024) {
        int i = base + tid;
        int v = (i < NN) ? g_cnt[i] : 0;
        int x = v;
#pragma unroll
        for (int o = 1; o < 32; o <<= 1) {
            int t = __shfl_up_sync(0xffffffffu, x, o);
            if (lane >= o) x += t;
        }
        if (lane == 31) warpsum[wid] = x;
        __syncthreads();
        if (wid == 0) {
            int w = warpsum[lane];
#pragma unroll
            for (int o = 1; o < 32; o <<= 1) {
                int t = __shfl_up_sync(0xffffffffu, w, o);
                if (lane >= o) w += t;
            }
            warpsum[lane] = w;
        }
        __syncthreads();
        int incl = s_total + (wid ? warpsum[wid - 1] : 0) + x;
        if (i < NN) {
            g_rowptr[i + 1] = incl;
            g_wptr[i] = incl - v;
        }
        __syncthreads();
        if (tid == 0) s_total += warpsum[31];
        __syncthreads();
    }
}
__global__ void csr_scatter_kernel(const int* __restrict__ ei) {
    int e = blockIdx.x * blockDim.x + threadIdx.x;
    if (e < EE) {
        int d = ei[EE + e];
        int pos = atomicAdd(&g_wptr[d], 1);
        g_csr[pos] = make_int2(e, ei[e]);
        g_csr_dst[pos] = d;
    }
}

// ---------------- xl/xr GEMM: 64x128 tile, 4x8/thread, FFMA2, 3 blocks/SM ----------
#define TM 64
#define TN 128
#define TK 16
#define LIN_SMEM (2 * TK * TM * 8 + 2 * TK * TN * 4)
__global__ __launch_bounds__(256, 3) void lin_kernel(
    const float* __restrict__ Wl, const float* __restrict__ bl,
    const float* __restrict__ Wr, const float* __restrict__ br) {
    extern __shared__ char smem_raw[];
    u64*   sA2 = (u64*)smem_raw;                         // [2][TK][TM] dup pairs
    float* sB  = (float*)(smem_raw + 2 * TK * TM * 8);   // [2][TK][TN]
    const float* W  = blockIdx.y ? Wr : Wl;
    const float* bv = blockIdx.y ? br : bl;
    float* dst = blockIdx.y ? g_xr : g_xl;
    int m0 = blockIdx.x * TM;
    int tid = threadIdx.x;
    int tn = tid & 15, tm = tid >> 4;

    u64 acc[4][4];
#pragma unroll
    for (int i = 0; i < 4; i++)
#pragma unroll
        for (int j = 0; j < 4; j++) acc[i][j] = 0ull;

    float4 ra, rb[2];

#define LDG_AB(kc)                                                              \
    {                                                                           \
        int m = tid >> 2, kq = (tid & 3) << 2;                                  \
        int gm = m0 + m;                                                        \
        ra = make_float4(0.f, 0.f, 0.f, 0.f);                                   \
        if (gm < NN)                                                            \
            ra = *(const float4*)&g_h[gm * DD + (kc) * TK + kq];                \
        _Pragma("unroll")                                                       \
        for (int r = 0; r < 2; r++) {                                           \
            int idx = tid + r * 256;                                            \
            int k = idx >> 5, nq = (idx & 31) << 2;                             \
            rb[r] = *(const float4*)&W[((kc) * TK + k) * DD + nq];              \
        }                                                                       \
    }
#define STS_AB(buf)                                                             \
    {                                                                           \
        int m = tid >> 2, kq = (tid & 3) << 2;                                  \
        u64* pa = sA2 + (buf) * TK * TM;                                        \
        pa[(kq + 0) * TM + m] = dup2(ra.x);                                     \
        pa[(kq + 1) * TM + m] = dup2(ra.y);                                     \
        pa[(kq + 2) * TM + m] = dup2(ra.z);                                     \
        pa[(kq + 3) * TM + m] = dup2(ra.w);                                     \
        _Pragma("unroll")                                                       \
        for (int r = 0; r < 2; r++) {                                           \
            int idx = tid + r * 256;                                            \
            int k = idx >> 5, nq = (idx & 31) << 2;                             \
            *(float4*)&sB[((buf) * TK + k) * TN + nq] = rb[r];                  \
        }                                                                       \
    }

    LDG_AB(0);
    STS_AB(0);
    __syncthreads();
#pragma unroll
    for (int kc = 0; kc < DD / TK; kc++) {
        int buf = kc & 1;
        if (kc + 1 < DD / TK) LDG_AB(kc + 1);
#pragma unroll
        for (int kk = 0; kk < TK; kk++) {
            const u64* pa = sA2 + (buf * TK + kk) * TM + tm * 4;
            const u64* pb = (const u64*)&sB[(buf * TK + kk) * TN];
            u64 ap[4], bp[4];
#pragma unroll
            for (int i = 0; i < 4; i++) ap[i] = pa[i];
            bp[0] = pb[tn * 2];
            bp[1] = pb[tn * 2 + 1];
            bp[2] = pb[32 + tn * 2];
            bp[3] = pb[32 + tn * 2 + 1];
#pragma unroll
            for (int i = 0; i < 4; i++)
#pragma unroll
                for (int j = 0; j < 4; j++)
                    acc[i][j] = ffma2(ap[i], bp[j], acc[i][j]);
        }
        if (kc + 1 < DD / TK) {
            __syncthreads();
            STS_AB(buf ^ 1);
            __syncthreads();
        }
    }
    // epilogue
    float4 bias0 = *(const float4*)&bv[tn * 4];
    float4 bias1 = *(const float4*)&bv[64 + tn * 4];
#pragma unroll
    for (int i = 0; i < 4; i++) {
        int gm = m0 + tm * 4 + i;
        if (gm < NN) {
            float2 c0 = unpack2(acc[i][0]);
            float2 c1 = unpack2(acc[i][1]);
            float2 c2 = unpack2(acc[i][2]);
            float2 c3 = unpack2(acc[i][3]);
            float4 o0 = make_float4(c0.x + bias0.x, c0.y + bias0.y,
                                    c1.x + bias0.z, c1.y + bias0.w);
            float4 o1 = make_float4(c2.x + bias1.x, c2.y + bias1.y,
                                    c3.x + bias1.z, c3.y + bias1.w);
            *(float4*)&dst[gm * DD + tn * 4] = o0;
            *(float4*)&dst[gm * DD + 64 + tn * 4] = o1;
        }
    }
#undef LDG_AB
#undef STS_AB
}

// ---------------- pass A: tf32 TC ee GEMM + logits + exp, CSR-slot edge order ------
// (R6 non-persistent form: 3125 blocks, 128 edges each)
#define PA_EDGES 128
#define EFS 68   // padded k-stride (bank-conflict-free fragment loads)
#define PASSA_SMEM (PA_EDGES * EFS * 4 + DD * EFS * 4 + DD * 4)
__global__ __launch_bounds__(256, 3) void passA_kernel(const float* __restrict__ We,
                                                       const float* __restrict__ att) {
    extern __shared__ char smem_raw[];
    uint32_t* sEf  = (uint32_t*)smem_raw;                          // [128][EFS] tf32
    uint32_t* sWeT = (uint32_t*)(smem_raw + PA_EDGES * EFS * 4);   // [128 n][EFS k]
    float*    sAtt = (float*)   (smem_raw + PA_EDGES * EFS * 4 + DD * EFS * 4);
    __shared__ int sSrc[PA_EDGES], sDst[PA_EDGES];
    int tid = threadIdx.x;
    int eb = blockIdx.x * PA_EDGES;

    if (tid < PA_EDGES) {
        int2 c = g_csr[eb + tid];
        sSrc[tid] = c.y;
        sDst[tid] = g_csr_dst[eb + tid];
    }
    // stage We transposed (k-major -> [n][k]) as tf32
    for (int idx = tid; idx < EH * DD; idx += 256) {
        int k = idx >> 7, n = idx & 127;
        sWeT[n * EFS + k] = to_tf32(We[idx]);
    }
    if (tid < DD) sAtt[tid] = att[tid];
    // stage ef tile (rows gathered by original edge id) as tf32
    for (int idx = tid; idx < PA_EDGES * (EH / 4); idx += 256) {
        int r = idx >> 4, c4 = (idx & 15) << 2;
        int e = g_csr[eb + r].x;
        float4 v = *(const float4*)&g_ef[(size_t)e * EH + c4];
        uint4 t;
        t.x = to_tf32(v.x); t.y = to_tf32(v.y);
        t.z = to_tf32(v.z); t.w = to_tf32(v.w);
        *(uint4*)&sEf[r * EFS + c4] = t;
    }
    __syncthreads();

    int lane = tid & 31, wm = tid >> 5;
    int gid = lane >> 2, q = lane & 3;

    int r0 = wm * 16 + gid;
    int r1 = r0 + 8;
    const float* xl0 = g_xl + (size_t)sSrc[r0] * DD;
    const float* xr0 = g_xr + (size_t)sDst[r0] * DD;
    const float* xl1 = g_xl + (size_t)sSrc[r1] * DD;
    const float* xr1 = g_xr + (size_t)sDst[r1] * DD;
    const uint32_t* efr0 = sEf + r0 * EFS;
    const uint32_t* efr1 = sEf + r1 * EFS;

    float h0[8], h1[8];
#pragma unroll
    for (int h = 0; h < 8; h++) { h0[h] = 0.f; h1[h] = 0.f; }

#pragma unroll
    for (int half = 0; half < 2; half++) {
        float d[8][4];
#pragma unroll
        for (int n8 = 0; n8 < 8; n8++)
#pragma unroll
            for (int j = 0; j < 4; j++) d[n8][j] = 0.f;

#pragma unroll
        for (int k0 = 0; k0 < 8; k0++) {
            uint32_t a0 = efr0[k0 * 8 + q];
            uint32_t a1 = efr1[k0 * 8 + q];
            uint32_t a2 = efr0[k0 * 8 + q + 4];
            uint32_t a3 = efr1[k0 * 8 + q + 4];
#pragma unroll
            for (int n8 = 0; n8 < 8; n8++) {
                int n = half * 8 + n8;
                uint32_t b0 = sWeT[(n * 8 + gid) * EFS + k0 * 8 + q];
                uint32_t b1 = sWeT[(n * 8 + gid) * EFS + k0 * 8 + q + 4];
                asm volatile(
                    "mma.sync.aligned.m16n8k8.row.col.f32.tf32.tf32.f32 "
                    "{%0,%1,%2,%3}, {%4,%5,%6,%7}, {%8,%9}, {%0,%1,%2,%3};"
                    : "+f"(d[n8][0]), "+f"(d[n8][1]), "+f"(d[n8][2]), "+f"(d[n8][3])
                    : "r"(a0), "r"(a1), "r"(a2), "r"(a3), "r"(b0), "r"(b1));
            }
        }
#pragma unroll
        for (int n8 = 0; n8 < 8; n8++) {
            int n = half * 8 + n8;
            int c = n * 8 + q * 2;
            float2 av  = *(const float2*)&sAtt[c];
            float2 l0v = *(const float2*)&xl0[c];
            float2 r0v = *(const float2*)&xr0[c];
            float2 l1v = *(const float2*)&xl1[c];
            float2 r1v = *(const float2*)&xr1[c];
            float v00 = d[n8][0] + l0v.x + r0v.x; v00 = v00 > 0.f ? v00 : 0.2f * v00;
            float v01 = d[n8][1] + l0v.y + r0v.y; v01 = v01 > 0.f ? v01 : 0.2f * v01;
            float v10 = d[n8][2] + l1v.x + r1v.x; v10 = v10 > 0.f ? v10 : 0.2f * v10;
            float v11 = d[n8][3] + l1v.y + r1v.y; v11 = v11 > 0.f ? v11 : 0.2f * v11;
            h0[n >> 1] += v00 * av.x + v01 * av.y;
            h1[n >> 1] += v10 * av.x + v11 * av.y;
        }
    }
#pragma unroll
    for (int h = 0; h < 8; h++) {
        h0[h] += __shfl_xor_sync(0xffffffffu, h0[h], 1);
        h0[h] += __shfl_xor_sync(0xffffffffu, h0[h], 2);
        h1[h] += __shfl_xor_sync(0xffffffffu, h1[h], 1);
        h1[h] += __shfl_xor_sync(0xffffffffu, h1[h], 2);
    }
    size_t p0 = (size_t)(eb + r0) * HH;
    size_t p1 = (size_t)(eb + r1) * HH;
    g_a[p0 + 2 * q]     = expf(h0[2 * q]);
    g_a[p0 + 2 * q + 1] = expf(h0[2 * q + 1]);
    g_a[p1 + 2 * q]     = expf(h1[2 * q]);
    g_a[p1 + 2 * q + 1] = expf(h1[2 * q + 1]);
}

// ---------------- pass B: per-dst gather (no atomics) + fused residual+LN+relu -----
__global__ void passB_kernel(const float* __restrict__ cb,
                             const float* __restrict__ g,
                             const float* __restrict__ beta) {
    int node = (blockIdx.x * blockDim.x + threadIdx.x) >> 5;
    int lane = threadIdx.x & 31;
    if (node >= NN) return;
    int start = g_rowptr[node], end = g_rowptr[node + 1];

    // denominator: sum over in-edge slots per head (coalesced: 4 slots x 8 heads)
    float s = 0.f;
    for (int p0 = start; p0 < end; p0 += 4) {
        int p = p0 + (lane >> 3);
        if (p < end) s += g_a[(size_t)p * HH + (lane & 7)];
    }
    s += __shfl_xor_sync(0xffffffffu, s, 8);
    s += __shfl_xor_sync(0xffffffffu, s, 16);
    float sh = __shfl_sync(0xffffffffu, s, lane >> 2);
    float rinv = 1.0f / (sh + 1e-16f);

    // weighted aggregation of xl[src], 4-way unrolled for MLP
    int head = lane >> 2;
    float4 acc = make_float4(0.f, 0.f, 0.f, 0.f);
    int p = start;
    for (; p + 4 <= end; p += 4) {
        int s0 = g_csr[p].y,     s1 = g_csr[p + 1].y;
        int s2 = g_csr[p + 2].y, s3 = g_csr[p + 3].y;
        float a0 = g_a[(size_t)(p)     * HH + head];
        float a1 = g_a[(size_t)(p + 1) * HH + head];
        float a2 = g_a[(size_t)(p + 2) * HH + head];
        float a3 = g_a[(size_t)(p + 3) * HH + head];
        float4 x0 = *(const float4*)&g_xl[(size_t)s0 * DD + 4 * lane];
        float4 x1 = *(const float4*)&g_xl[(size_t)s1 * DD + 4 * lane];
        float4 x2 = *(const float4*)&g_xl[(size_t)s2 * DD + 4 * lane];
        float4 x3 = *(const float4*)&g_xl[(size_t)s3 * DD + 4 * lane];
        acc.x += a0 * x0.x + a1 * x1.x + a2 * x2.x + a3 * x3.x;
        acc.y += a0 * x0.y + a1 * x1.y + a2 * x2.y + a3 * x3.y;
        acc.z += a0 * x0.z + a1 * x1.z + a2 * x2.z + a3 * x3.z;
        acc.w += a0 * x0.w + a1 * x1.w + a2 * x2.w + a3 * x3.w;
    }
    for (; p < end; p++) {
        int sn = g_csr[p].y;
        float al = g_a[(size_t)p * HH + head];
        float4 xv = *(const float4*)&g_xl[(size_t)sn * DD + 4 * lane];
        acc.x += al * xv.x; acc.y += al * xv.y;
        acc.z += al * xv.z; acc.w += al * xv.w;
    }
    acc.x *= rinv; acc.y *= rinv; acc.z *= rinv; acc.w *= rinv;

    // residual + conv bias, then LN + relu, write back to g_h
    int d0 = 4 * lane;
    float4 hv = *(const float4*)&g_h[node * DD + d0];
    float4 cv = *(const float4*)&cb[d0];
    float a0 = acc.x + cv.x + hv.x;
    float a1 = acc.y + cv.y + hv.y;
    float a2 = acc.z + cv.z + hv.z;
    float a3 = acc.w + cv.w + hv.w;
    float m = warp_sum(a0 + a1 + a2 + a3) * (1.0f / DD);
    float e0d = a0 - m, e1d = a1 - m, e2d = a2 - m, e3d = a3 - m;
    float v = warp_sum(e0d * e0d + e1d * e1d + e2d * e2d + e3d * e3d) * (1.0f / DD);
    float rstd = rsqrtf(v + 1e-5f);
    float4 gv = *(const float4*)&g[d0];
    float4 bv = *(const float4*)&beta[d0];
    float4 o;
    o.x = fmaxf(e0d * rstd * gv.x + bv.x, 0.f);
    o.y = fmaxf(e1d * rstd * gv.y + bv.y, 0.f);
    o.z = fmaxf(e2d * rstd * gv.z + bv.z, 0.f);
    o.w = fmaxf(e3d * rstd * gv.w + bv.w, 0.f);
    *(float4*)&g_h[node * DD + d0] = o;
}

// ---------------- head: relu(h@W1+b1) @ W2 -> sigmoid. 1 warp/node -----------------
__global__ void head_kernel(float* __restrict__ out,
                            const float* __restrict__ W1, const float* __restrict__ b1,
                            const float* __restrict__ W2, const float* __restrict__ b2) {
    int warp = (blockIdx.x * blockDim.x + threadIdx.x) >> 5;
    int lane = threadIdx.x & 31;
    if (warp >= NN) return;
    float hr[4];
#pragma unroll
    for (int q = 0; q < 4; q++) hr[q] = g_h[warp * DD + q * 32 + lane];
    float z0 = b1[lane], z1 = b1[lane + 32];
#pragma unroll
    for (int q = 0; q < 4; q++) {
#pragma unroll 8
        for (int kk = 0; kk < 32; kk++) {
            float hk = __shfl_sync(0xffffffffu, hr[q], kk);
            int k = q * 32 + kk;
            z0 += hk * W1[k * 64 + lane];
            z1 += hk * W1[k * 64 + 32 + lane];
        }
    }
    z0 = fmaxf(z0, 0.f);
    z1 = fmaxf(z1, 0.f);
    float p = z0 * W2[lane] + z1 * W2[lane + 32];
    p = warp_sum(p);
    if (lane == 0) out[warp] = 1.0f / (1.0f + expf(-(p + b2[0])));
}

// ---------------- launch ----------------------------------------------------------
extern "C" void kernel_launch(void* const* d_in, const int* in_sizes, int n_in,
                              void* d_out, int out_size) {
    const float* x    = (const float*)d_in[0];
    const int*   ei   = (const int*)  d_in[1];
    const float* ea   = (const float*)d_in[2];
    const float* neW  = (const float*)d_in[3];
    const float* neb  = (const float*)d_in[4];
    const float* neg  = (const float*)d_in[5];
    const float* nebt = (const float*)d_in[6];
    const float* eeW  = (const float*)d_in[7];
    const float* eeb  = (const float*)d_in[8];
    const float* eeg  = (const float*)d_in[9];
    const float* eebt = (const float*)d_in[10];
    const float* Wl   = (const float*)d_in[11];
    const float* bl   = (const float*)d_in[12];
    const float* Wr   = (const float*)d_in[13];
    const float* br   = (const float*)d_in[14];
    const float* We   = (const float*)d_in[15];
    const float* att  = (const float*)d_in[16];
    const float* cb   = (const float*)d_in[17];
    const float* lng  = (const float*)d_in[18];
    const float* lnb  = (const float*)d_in[19];
    const float* W1   = (const float*)d_in[20];
    const float* b1   = (const float*)d_in[21];
    const float* W2   = (const float*)d_in[22];
    const float* b2   = (const float*)d_in[23];
    float* out = (float*)d_out;

    cudaFuncSetAttribute(lin_kernel, cudaFuncAttributeMaxDynamicSharedMemorySize,
                         LIN_SMEM);
    cudaFuncSetAttribute(passA_kernel, cudaFuncAttributeMaxDynamicSharedMemorySize,
                         PASSA_SMEM);

    dim3 lin_grid((NN + TM - 1) / TM, 2);
    int passa_grid = EE / PA_EDGES;

    // index 3 = lin_kernel (layer 0) so ncu profiles the new 64x128 GEMM
    node_enc_kernel<<<NN / 8, 256>>>(x, neW, neb, neg, nebt);                    // 0
    csr_zero_kernel<<<(NN + 255) / 256, 256>>>();                                // 1
    csr_count_kernel<<<(EE + 255) / 256, 256>>>(ei);                             // 2
    lin_kernel<<<lin_grid, 256, LIN_SMEM>>>(Wl, bl, Wr, br);                     // 3
    csr_scan_kernel<<<1, 1024>>>();                                              // 4
    csr_scatter_kernel<<<(EE + 255) / 256, 256>>>(ei);                           // 5
    edge_enc_kernel<<<EE / 8, 256>>>(ea, eeW, eeb, eeg, eebt);                   // 6

    for (int l = 0; l < LL; l++) {
        if (l > 0)
            lin_kernel<<<lin_grid, 256, LIN_SMEM>>>(Wl + l * DD * DD, bl + l * DD,
                                                    Wr + l * DD * DD, br + l * DD);
        passA_kernel<<<passa_grid, 256, PASSA_SMEM>>>(We + l * EH * DD,
                                                      att + l * HH * CC);
        passB_kernel<<<(NN * 32 + 255) / 256, 256>>>(cb + l * DD, lng + l * DD,
                                                     lnb + l * DD);
    }
    head_kernel<<<NN / 8, 256>>>(out, W1, b1, W2, b2);
}

// round 9
// speedup vs baseline: 1.0716x; 1.0635x over previous
#include <cuda_runtime.h>
#include <math.h>
#include <stdint.h>

#define NN 50000
#define EE 400000
#define DD 128
#define HH 8
#define CC 16
#define EH 64
#define LL 6

static_assert(EE % 128 == 0, "edge tiling");
static_assert(NN % 8 == 0, "node tiling");

// ---------------- device scratch (static; no allocations allowed) ----------------
__device__ __align__(16) float g_h  [NN * DD];   // node features
__device__ __align__(16) float g_xl [NN * DD];   // lin_l output
__device__ __align__(16) float g_xr [NN * DD];   // lin_r output
__device__ __align__(16) float g_ef [EE * EH];   // encoded edge features
__device__             float g_a   [EE * HH];    // exp(logit), indexed by CSR SLOT
// CSR by destination node (built once per launch)
__device__ int  g_cnt   [NN];
__device__ int  g_wptr  [NN];
__device__ int  g_rowptr[NN + 1];
__device__ int2 g_csr    [EE];   // (orig edge id, src node) per slot
__device__ int  g_csr_dst[EE];   // dst node per slot

typedef unsigned long long u64;

__device__ __forceinline__ float warp_sum(float v) {
#pragma unroll
    for (int o = 16; o; o >>= 1) v += __shfl_xor_sync(0xffffffffu, v, o);
    return v;
}
// ---- packed f32x2 helpers (sm_100a) ----
__device__ __forceinline__ u64 dup2(float v) {
    u64 r; asm("mov.b64 %0, {%1, %1};" : "=l"(r) : "f"(v)); return r;
}
__device__ __forceinline__ u64 ffma2(u64 a, u64 b, u64 c) {
    u64 d; asm("fma.rn.f32x2 %0, %1, %2, %3;" : "=l"(d) : "l"(a), "l"(b), "l"(c));
    return d;
}
__device__ __forceinline__ float2 unpack2(u64 p) {
    float2 r; asm("mov.b64 {%0, %1}, %2;" : "=f"(r.x), "=f"(r.y) : "l"(p));
    return r;
}
__device__ __forceinline__ uint32_t to_tf32(float f) {
    uint32_t t; asm("cvt.rna.tf32.f32 %0, %1;" : "=r"(t) : "f"(f)); return t;
}
__device__ __forceinline__ u64 pack2u(uint32_t lo, uint32_t hi) {
    return ((u64)hi << 32) | (u64)lo;
}

// ---------------- node encoder: x(N,9) -> LN -> relu -> g_h(N,128). 1 warp/node ----
__global__ void node_enc_kernel(const float* __restrict__ x,
                                const float* __restrict__ W,
                                const float* __restrict__ b,
                                const float* __restrict__ g,
                                const float* __restrict__ beta) {
    int warp = (blockIdx.x * blockDim.x + threadIdx.x) >> 5;
    int lane = threadIdx.x & 31;
    if (warp >= NN) return;
    float acc[4];
#pragma unroll
    for (int j = 0; j < 4; j++) acc[j] = b[lane + 32 * j];
#pragma unroll
    for (int k = 0; k < 9; k++) {
        float xv = x[warp * 9 + k];
#pragma unroll
        for (int j = 0; j < 4; j++) acc[j] += xv * W[k * DD + lane + 32 * j];
    }
    float s = 0.f;
#pragma unroll
    for (int j = 0; j < 4; j++) s += acc[j];
    float m = warp_sum(s) * (1.0f / DD);
    float v = 0.f;
#pragma unroll
    for (int j = 0; j < 4; j++) { float d = acc[j] - m; v += d * d; }
    v = warp_sum(v) * (1.0f / DD);
    float rstd = rsqrtf(v + 1e-5f);
#pragma unroll
    for (int j = 0; j < 4; j++) {
        int d = lane + 32 * j;
        float y = (acc[j] - m) * rstd * g[d] + beta[d];
        g_h[warp * DD + d] = fmaxf(y, 0.0f);
    }
}

// ---------------- edge encoder: edge_attr(E,3) -> LN -> relu -> g_ef(E,64) ---------
__global__ void edge_enc_kernel(const float* __restrict__ ea,
                                const float* __restrict__ W,
                                const float* __restrict__ b,
                                const float* __restrict__ g,
                                const float* __restrict__ beta) {
    int warp = (blockIdx.x * blockDim.x + threadIdx.x) >> 5;
    int lane = threadIdx.x & 31;
    if (warp >= EE) return;
    float a0 = b[lane], a1 = b[lane + 32];
#pragma unroll
    for (int k = 0; k < 3; k++) {
        float xv = ea[warp * 3 + k];
        a0 += xv * W[k * EH + lane];
        a1 += xv * W[k * EH + 32 + lane];
    }
    float m = warp_sum(a0 + a1) * (1.0f / EH);
    float d0 = a0 - m, d1 = a1 - m;
    float v = warp_sum(d0 * d0 + d1 * d1) * (1.0f / EH);
    float rstd = rsqrtf(v + 1e-5f);
    float y0 = d0 * rstd * g[lane] + beta[lane];
    float y1 = d1 * rstd * g[lane + 32] + beta[lane + 32];
    g_ef[warp * EH + lane]      = fmaxf(y0, 0.f);
    g_ef[warp * EH + 32 + lane] = fmaxf(y1, 0.f);
}

// ---------------- CSR build (once per launch) --------------------------------------
__global__ void csr_zero_kernel() {
    int i = blockIdx.x * blockDim.x + threadIdx.x;
    if (i < NN) g_cnt[i] = 0;
}
__global__ void csr_count_kernel(const int* __restrict__ ei) {
    int e = blockIdx.x * blockDim.x + threadIdx.x;
    if (e < EE) atomicAdd(&g_cnt[ei[EE + e]], 1);
}
__global__ void csr_scan_kernel() {
    __shared__ int warpsum[32];
    __shared__ int s_total;
    int tid = threadIdx.x, lane = tid & 31, wid = tid >> 5;
    if (tid == 0) { s_total = 0; g_rowptr[0] = 0; }
    __syncthreads();
    for (int base = 0; base < NN; base += 1024) {
        int i = base + tid;
        int v = (i < NN) ? g_cnt[i] : 0;
        int x = v;
#pragma unroll
        for (int o = 1; o < 32; o <<= 1) {
            int t = __shfl_up_sync(0xffffffffu, x, o);
            if (lane >= o) x += t;
        }
        if (lane == 31) warpsum[wid] = x;
        __syncthreads();
        if (wid == 0) {
            int w = warpsum[lane];
#pragma unroll
            for (int o = 1; o < 32; o <<= 1) {
                int t = __shfl_up_sync(0xffffffffu, w, o);
                if (lane >= o) w += t;
            }
            warpsum[lane] = w;
        }
        __syncthreads();
        int incl = s_total + (wid ? warpsum[wid - 1] : 0) + x;
        if (i < NN) {
            g_rowptr[i + 1] = incl;
            g_wptr[i] = incl - v;
        }
        __syncthreads();
        if (tid == 0) s_total += warpsum[31];
        __syncthreads();
    }
}
__global__ void csr_scatter_kernel(const int* __restrict__ ei) {
    int e = blockIdx.x * blockDim.x + threadIdx.x;
    if (e < EE) {
        int d = ei[EE + e];
        int pos = atomicAdd(&g_wptr[d], 1);
        g_csr[pos] = make_int2(e, ei[e]);
        g_csr_dst[pos] = d;
    }
}

// ---------------- xl/xr GEMM: 128x128 tile, 8x8/thread, FFMA2 (R7 proven form) -----
#define TM 128
#define TN 128
#define TK 16
#define LIN_SMEM (2 * TK * TM * 8 + 2 * TK * TN * 4)
__global__ __launch_bounds__(256, 2) void lin_kernel(
    const float* __restrict__ Wl, const float* __restrict__ bl,
    const float* __restrict__ Wr, const float* __restrict__ br) {
    extern __shared__ char smem_raw[];
    u64*   sA2 = (u64*)smem_raw;                         // [2][TK][TM] dup pairs
    float* sB  = (float*)(smem_raw + 2 * TK * TM * 8);   // [2][TK][TN]
    const float* W  = blockIdx.y ? Wr : Wl;
    const float* bv = blockIdx.y ? br : bl;
    float* dst = blockIdx.y ? g_xr : g_xl;
    int m0 = blockIdx.x * TM;
    int tid = threadIdx.x;
    int tn = tid & 15, tm = tid >> 4;

    u64 acc[8][4];
#pragma unroll
    for (int i = 0; i < 8; i++)
#pragma unroll
        for (int j = 0; j < 4; j++) acc[i][j] = 0ull;

    float4 ra[2], rb[2];

#define LDG_AB(kc)                                                              \
    {                                                                           \
        _Pragma("unroll")                                                       \
        for (int r = 0; r < 2; r++) {                                           \
            int idx = tid + r * 256;                                            \
            int m = idx >> 2, kq = (idx & 3) << 2;                              \
            int gm = m0 + m;                                                    \
            ra[r] = make_float4(0.f, 0.f, 0.f, 0.f);                            \
            if (gm < NN)                                                        \
                ra[r] = *(const float4*)&g_h[gm * DD + (kc) * TK + kq];         \
            int k = idx >> 5, nq = (idx & 31) << 2;                             \
            rb[r] = *(const float4*)&W[((kc) * TK + k) * DD + nq];              \
        }                                                                       \
    }
#define STS_AB(buf)                                                             \
    {                                                                           \
        _Pragma("unroll")                                                       \
        for (int r = 0; r < 2; r++) {                                           \
            int idx = tid + r * 256;                                            \
            int m = idx >> 2, kq = (idx & 3) << 2;                              \
            u64* pa = sA2 + (buf) * TK * TM;                                    \
            pa[(kq + 0) * TM + m] = dup2(ra[r].x);                              \
            pa[(kq + 1) * TM + m] = dup2(ra[r].y);                              \
            pa[(kq + 2) * TM + m] = dup2(ra[r].z);                              \
            pa[(kq + 3) * TM + m] = dup2(ra[r].w);                              \
            int k = idx >> 5, nq = (idx & 31) << 2;                             \
            *(float4*)&sB[((buf) * TK + k) * TN + nq] = rb[r];                  \
        }                                                                       \
    }

    LDG_AB(0);
    STS_AB(0);
    __syncthreads();
#pragma unroll
    for (int kc = 0; kc < DD / TK; kc++) {
        int buf = kc & 1;
        if (kc + 1 < DD / TK) LDG_AB(kc + 1);
#pragma unroll
        for (int kk = 0; kk < TK; kk++) {
            const u64* pa = sA2 + (buf * TK + kk) * TM + tm * 8;
            const u64* pb = (const u64*)&sB[(buf * TK + kk) * TN];
            u64 ap[8], bp[4];
#pragma unroll
            for (int i = 0; i < 8; i++) ap[i] = pa[i];
            bp[0] = pb[tn * 2];
            bp[1] = pb[tn * 2 + 1];
            bp[2] = pb[32 + tn * 2];
            bp[3] = pb[32 + tn * 2 + 1];
#pragma unroll
            for (int i = 0; i < 8; i++)
#pragma unroll
                for (int j = 0; j < 4; j++)
                    acc[i][j] = ffma2(ap[i], bp[j], acc[i][j]);
        }
        if (kc + 1 < DD / TK) {
            __syncthreads();
            STS_AB(buf ^ 1);
            __syncthreads();
        }
    }
    // epilogue
    float4 bias0 = *(const float4*)&bv[tn * 4];
    float4 bias1 = *(const float4*)&bv[64 + tn * 4];
#pragma unroll
    for (int i = 0; i < 8; i++) {
        int gm = m0 + tm * 8 + i;
        if (gm < NN) {
            float2 c0 = unpack2(acc[i][0]);
            float2 c1 = unpack2(acc[i][1]);
            float2 c2 = unpack2(acc[i][2]);
            float2 c3 = unpack2(acc[i][3]);
            float4 o0 = make_float4(c0.x + bias0.x, c0.y + bias0.y,
                                    c1.x + bias0.z, c1.y + bias0.w);
            float4 o1 = make_float4(c2.x + bias1.x, c2.y + bias1.y,
                                    c3.x + bias1.z, c3.y + bias1.w);
            *(float4*)&dst[gm * DD + tn * 4] = o0;
            *(float4*)&dst[gm * DD + 64 + tn * 4] = o1;
        }
    }
#undef LDG_AB
#undef STS_AB
}

// ---------------- pass A: tf32 TC ee GEMM, paired-u64 fragments (LDS.64) -----------
// 128 CSR-slot edges/block, 8 warps, 16 edges/warp; two halves of 8 accum chains.
// Fragment pairs (k, k+4) stored as one u64 -> half the LDS issues, same bytes.
#define PA_EDGES 128
#define EFS2 36   // u64 stride per row: 32 pairs + 4 pad (conflict-free per half-warp)
#define PASSA_SMEM (PA_EDGES * EFS2 * 8 + DD * EFS2 * 8 + DD * 4)
__global__ __launch_bounds__(256, 3) void passA_kernel(const float* __restrict__ We,
                                                       const float* __restrict__ att) {
    extern __shared__ char smem_raw[];
    u64*   sEf2 = (u64*)smem_raw;                            // [128 rows][EFS2] pairs
    u64*   sWe2 = (u64*)(smem_raw + PA_EDGES * EFS2 * 8);    // [128 n][EFS2] pairs
    float* sAtt = (float*)(smem_raw + PA_EDGES * EFS2 * 8 + DD * EFS2 * 8);
    __shared__ int sSrc[PA_EDGES], sDst[PA_EDGES];
    int tid = threadIdx.x;
    int eb = blockIdx.x * PA_EDGES;

    if (tid < PA_EDGES) {
        int2 c = g_csr[eb + tid];
        sSrc[tid] = c.y;
        sDst[tid] = g_csr_dst[eb + tid];
    }
    if (tid < DD) sAtt[tid] = att[tid];
    // stage We as paired tf32: pair j of (n, k0) = (W[k0*8+j][n], W[k0*8+j+4][n])
    for (int idx = tid; idx < DD * (EH / 8); idx += 256) {   // 1024
        int n = idx & 127, k0 = idx >> 7;
        float w[8];
#pragma unroll
        for (int j = 0; j < 8; j++) w[j] = We[(k0 * 8 + j) * DD + n];
#pragma unroll
        for (int j = 0; j < 4; j++)
            sWe2[n * EFS2 + k0 * 4 + j] = pack2u(to_tf32(w[j]), to_tf32(w[j + 4]));
    }
    // stage ef tile (gathered by orig edge id) as paired tf32
    for (int idx = tid; idx < PA_EDGES * (EH / 8); idx += 256) {  // 1024
        int r = idx >> 3, k8 = (idx & 7) << 3;
        int e = g_csr[eb + r].x;
        float4 v0 = *(const float4*)&g_ef[(size_t)e * EH + k8];
        float4 v1 = *(const float4*)&g_ef[(size_t)e * EH + k8 + 4];
        u64* dst = sEf2 + r * EFS2 + (k8 >> 3) * 4;
        dst[0] = pack2u(to_tf32(v0.x), to_tf32(v1.x));
        dst[1] = pack2u(to_tf32(v0.y), to_tf32(v1.y));
        dst[2] = pack2u(to_tf32(v0.z), to_tf32(v1.z));
        dst[3] = pack2u(to_tf32(v0.w), to_tf32(v1.w));
    }
    __syncthreads();

    int lane = tid & 31, wm = tid >> 5;
    int gid = lane >> 2, q = lane & 3;

    int r0 = wm * 16 + gid;
    int r1 = r0 + 8;
    const float* xl0 = g_xl + (size_t)sSrc[r0] * DD;
    const float* xr0 = g_xr + (size_t)sDst[r0] * DD;
    const float* xl1 = g_xl + (size_t)sSrc[r1] * DD;
    const float* xr1 = g_xr + (size_t)sDst[r1] * DD;
    const u64* efr0 = sEf2 + r0 * EFS2;
    const u64* efr1 = sEf2 + r1 * EFS2;

    float h0[8], h1[8];
#pragma unroll
    for (int h = 0; h < 8; h++) { h0[h] = 0.f; h1[h] = 0.f; }

#pragma unroll
    for (int half = 0; half < 2; half++) {
        float d[8][4];
#pragma unroll
        for (int n8 = 0; n8 < 8; n8++)
#pragma unroll
            for (int j = 0; j < 4; j++) d[n8][j] = 0.f;

#pragma unroll
        for (int k0 = 0; k0 < 8; k0++) {
            u64 pa0 = efr0[k0 * 4 + q];   // (a0 = k q, a2 = k q+4) for row r0
            u64 pa1 = efr1[k0 * 4 + q];   // (a1, a3) for row r1
            uint32_t a0 = (uint32_t)pa0, a2 = (uint32_t)(pa0 >> 32);
            uint32_t a1 = (uint32_t)pa1, a3 = (uint32_t)(pa1 >> 32);
#pragma unroll
            for (int n8 = 0; n8 < 8; n8++) {
                int n = half * 8 + n8;
                u64 pb = sWe2[(n * 8 + gid) * EFS2 + k0 * 4 + q];
                uint32_t b0 = (uint32_t)pb, b1 = (uint32_t)(pb >> 32);
                asm volatile(
                    "mma.sync.aligned.m16n8k8.row.col.f32.tf32.tf32.f32 "
                    "{%0,%1,%2,%3}, {%4,%5,%6,%7}, {%8,%9}, {%0,%1,%2,%3};"
                    : "+f"(d[n8][0]), "+f"(d[n8][1]), "+f"(d[n8][2]), "+f"(d[n8][3])
                    : "r"(a0), "r"(a1), "r"(a2), "r"(a3), "r"(b0), "r"(b1));
            }
        }
#pragma unroll
        for (int n8 = 0; n8 < 8; n8++) {
            int n = half * 8 + n8;
            int c = n * 8 + q * 2;
            float2 av  = *(const float2*)&sAtt[c];
            float2 l0v = *(const float2*)&xl0[c];
            float2 r0v = *(const float2*)&xr0[c];
            float2 l1v = *(const float2*)&xl1[c];
            float2 r1v = *(const float2*)&xr1[c];
            float v00 = d[n8][0] + l0v.x + r0v.x; v00 = v00 > 0.f ? v00 : 0.2f * v00;
            float v01 = d[n8][1] + l0v.y + r0v.y; v01 = v01 > 0.f ? v01 : 0.2f * v01;
            float v10 = d[n8][2] + l1v.x + r1v.x; v10 = v10 > 0.f ? v10 : 0.2f * v10;
            float v11 = d[n8][3] + l1v.y + r1v.y; v11 = v11 > 0.f ? v11 : 0.2f * v11;
            h0[n >> 1] += v00 * av.x + v01 * av.y;
            h1[n >> 1] += v10 * av.x + v11 * av.y;
        }
    }
#pragma unroll
    for (int h = 0; h < 8; h++) {
        h0[h] += __shfl_xor_sync(0xffffffffu, h0[h], 1);
        h0[h] += __shfl_xor_sync(0xffffffffu, h0[h], 2);
        h1[h] += __shfl_xor_sync(0xffffffffu, h1[h], 1);
        h1[h] += __shfl_xor_sync(0xffffffffu, h1[h], 2);
    }
    size_t p0 = (size_t)(eb + r0) * HH;
    size_t p1 = (size_t)(eb + r1) * HH;
    g_a[p0 + 2 * q]     = expf(h0[2 * q]);
    g_a[p0 + 2 * q + 1] = expf(h0[2 * q + 1]);
    g_a[p1 + 2 * q]     = expf(h1[2 * q]);
    g_a[p1 + 2 * q + 1] = expf(h1[2 * q + 1]);
}

// ---------------- pass B: per-dst gather (no atomics) + fused residual+LN+relu -----
__global__ void passB_kernel(const float* __restrict__ cb,
                             const float* __restrict__ g,
                             const float* __restrict__ beta) {
    int node = (blockIdx.x * blockDim.x + threadIdx.x) >> 5;
    int lane = threadIdx.x & 31;
    if (node >= NN) return;
    int start = g_rowptr[node], end = g_rowptr[node + 1];

    float s = 0.f;
    for (int p0 = start; p0 < end; p0 += 4) {
        int p = p0 + (lane >> 3);
        if (p < end) s += g_a[(size_t)p * HH + (lane & 7)];
    }
    s += __shfl_xor_sync(0xffffffffu, s, 8);
    s += __shfl_xor_sync(0xffffffffu, s, 16);
    float sh = __shfl_sync(0xffffffffu, s, lane >> 2);
    float rinv = 1.0f / (sh + 1e-16f);

    int head = lane >> 2;
    float4 acc = make_float4(0.f, 0.f, 0.f, 0.f);
    int p = start;
    for (; p + 4 <= end; p += 4) {
        int s0 = g_csr[p].y,     s1 = g_csr[p + 1].y;
        int s2 = g_csr[p + 2].y, s3 = g_csr[p + 3].y;
        float a0 = g_a[(size_t)(p)     * HH + head];
        float a1 = g_a[(size_t)(p + 1) * HH + head];
        float a2 = g_a[(size_t)(p + 2) * HH + head];
        float a3 = g_a[(size_t)(p + 3) * HH + head];
        float4 x0 = *(const float4*)&g_xl[(size_t)s0 * DD + 4 * lane];
        float4 x1 = *(const float4*)&g_xl[(size_t)s1 * DD + 4 * lane];
        float4 x2 = *(const float4*)&g_xl[(size_t)s2 * DD + 4 * lane];
        float4 x3 = *(const float4*)&g_xl[(size_t)s3 * DD + 4 * lane];
        acc.x += a0 * x0.x + a1 * x1.x + a2 * x2.x + a3 * x3.x;
        acc.y += a0 * x0.y + a1 * x1.y + a2 * x2.y + a3 * x3.y;
        acc.z += a0 * x0.z + a1 * x1.z + a2 * x2.z + a3 * x3.z;
        acc.w += a0 * x0.w + a1 * x1.w + a2 * x2.w + a3 * x3.w;
    }
    for (; p < end; p++) {
        int sn = g_csr[p].y;
        float al = g_a[(size_t)p * HH + head];
        float4 xv = *(const float4*)&g_xl[(size_t)sn * DD + 4 * lane];
        acc.x += al * xv.x; acc.y += al * xv.y;
        acc.z += al * xv.z; acc.w += al * xv.w;
    }
    acc.x *= rinv; acc.y *= rinv; acc.z *= rinv; acc.w *= rinv;

    int d0 = 4 * lane;
    float4 hv = *(const float4*)&g_h[node * DD + d0];
    float4 cv = *(const float4*)&cb[d0];
    float a0 = acc.x + cv.x + hv.x;
    float a1 = acc.y + cv.y + hv.y;
    float a2 = acc.z + cv.z + hv.z;
    float a3 = acc.w + cv.w + hv.w;
    float m = warp_sum(a0 + a1 + a2 + a3) * (1.0f / DD);
    float e0d = a0 - m, e1d = a1 - m, e2d = a2 - m, e3d = a3 - m;
    float v = warp_sum(e0d * e0d + e1d * e1d + e2d * e2d + e3d * e3d) * (1.0f / DD);
    float rstd = rsqrtf(v + 1e-5f);
    float4 gv = *(const float4*)&g[d0];
    float4 bv = *(const float4*)&beta[d0];
    float4 o;
    o.x = fmaxf(e0d * rstd * gv.x + bv.x, 0.f);
    o.y = fmaxf(e1d * rstd * gv.y + bv.y, 0.f);
    o.z = fmaxf(e2d * rstd * gv.z + bv.z, 0.f);
    o.w = fmaxf(e3d * rstd * gv.w + bv.w, 0.f);
    *(float4*)&g_h[node * DD + d0] = o;
}

// ---------------- head: relu(h@W1+b1) @ W2 -> sigmoid. 1 warp/node -----------------
__global__ void head_kernel(float* __restrict__ out,
                            const float* __restrict__ W1, const float* __restrict__ b1,
                            const float* __restrict__ W2, const float* __restrict__ b2) {
    int warp = (blockIdx.x * blockDim.x + threadIdx.x) >> 5;
    int lane = threadIdx.x & 31;
    if (warp >= NN) return;
    float hr[4];
#pragma unroll
    for (int q = 0; q < 4; q++) hr[q] = g_h[warp * DD + q * 32 + lane];
    float z0 = b1[lane], z1 = b1[lane + 32];
#pragma unroll
    for (int q = 0; q < 4; q++) {
#pragma unroll 8
        for (int kk = 0; kk < 32; kk++) {
            float hk = __shfl_sync(0xffffffffu, hr[q], kk);
            int k = q * 32 + kk;
            z0 += hk * W1[k * 64 + lane];
            z1 += hk * W1[k * 64 + 32 + lane];
        }
    }
    z0 = fmaxf(z0, 0.f);
    z1 = fmaxf(z1, 0.f);
    float p = z0 * W2[lane] + z1 * W2[lane + 32];
    p = warp_sum(p);
    if (lane == 0) out[warp] = 1.0f / (1.0f + expf(-(p + b2[0])));
}

// ---------------- launch ----------------------------------------------------------
extern "C" void kernel_launch(void* const* d_in, const int* in_sizes, int n_in,
                              void* d_out, int out_size) {
    const float* x    = (const float*)d_in[0];
    const int*   ei   = (const int*)  d_in[1];
    const float* ea   = (const float*)d_in[2];
    const float* neW  = (const float*)d_in[3];
    const float* neb  = (const float*)d_in[4];
    const float* neg  = (const float*)d_in[5];
    const float* nebt = (const float*)d_in[6];
    const float* eeW  = (const float*)d_in[7];
    const float* eeb  = (const float*)d_in[8];
    const float* eeg  = (const float*)d_in[9];
    const float* eebt = (const float*)d_in[10];
    const float* Wl   = (const float*)d_in[11];
    const float* bl   = (const float*)d_in[12];
    const float* Wr   = (const float*)d_in[13];
    const float* br   = (const float*)d_in[14];
    const float* We   = (const float*)d_in[15];
    const float* att  = (const float*)d_in[16];
    const float* cb   = (const float*)d_in[17];
    const float* lng  = (const float*)d_in[18];
    const float* lnb  = (const float*)d_in[19];
    const float* W1   = (const float*)d_in[20];
    const float* b1   = (const float*)d_in[21];
    const float* W2   = (const float*)d_in[22];
    const float* b2   = (const float*)d_in[23];
    float* out = (float*)d_out;

    cudaFuncSetAttribute(lin_kernel, cudaFuncAttributeMaxDynamicSharedMemorySize,
                         LIN_SMEM);
    cudaFuncSetAttribute(passA_kernel, cudaFuncAttributeMaxDynamicSharedMemorySize,
                         PASSA_SMEM);

    dim3 lin_grid((NN + TM - 1) / TM, 2);
    int passa_grid = EE / PA_EDGES;

    node_enc_kernel<<<NN / 8, 256>>>(x, neW, neb, neg, nebt);                    // 0
    csr_zero_kernel<<<(NN + 255) / 256, 256>>>();                                // 1
    csr_count_kernel<<<(EE + 255) / 256, 256>>>(ei);                             // 2
    lin_kernel<<<lin_grid, 256, LIN_SMEM>>>(Wl, bl, Wr, br);                     // 3 (profiled)
    csr_scan_kernel<<<1, 1024>>>();                                              // 4
    csr_scatter_kernel<<<(EE + 255) / 256, 256>>>(ei);                           // 5
    edge_enc_kernel<<<EE / 8, 256>>>(ea, eeW, eeb, eeg, eebt);                   // 6

    for (int l = 0; l < LL; l++) {
        if (l > 0)
            lin_kernel<<<lin_grid, 256, LIN_SMEM>>>(Wl + l * DD * DD, bl + l * DD,
                                                    Wr + l * DD * DD, br + l * DD);
        passA_kernel<<<passa_grid, 256, PASSA_SMEM>>>(We + l * EH * DD,
                                                      att + l * HH * CC);
        passB_kernel<<<(NN * 32 + 255) / 256, 256>>>(cb + l * DD, lng + l * DD,
                                                     lnb + l * DD);
    }
    head_kernel<<<NN / 8, 256>>>(out, W1, b1, W2, b2);
}

// round 10
// speedup vs baseline: 1.1169x; 1.0422x over previous
#include <cuda_runtime.h>
#include <math.h>
#include <stdint.h>

#define NN 50000
#define EE 400000
#define DD 128
#define HH 8
#define CC 16
#define EH 64
#define LL 6

static_assert(EE % 128 == 0, "edge tiling");
static_assert(NN % 8 == 0, "node tiling");

// ---------------- device scratch (static; no allocations allowed) ----------------
__device__ __align__(16) float g_h  [NN * DD];   // node features
__device__ __align__(16) float g_xl [NN * DD];   // lin_l output (fp32, exact)
__device__ __align__(16) float g_xr [NN * DD];   // lin_r output (fp32, exact)
__device__ __align__(8) uint32_t g_xlh[NN * 64]; // bf16x2 mirror of xl (for passA)
__device__ __align__(8) uint32_t g_xrh[NN * 64]; // bf16x2 mirror of xr (for passA)
__device__ __align__(16) float g_ef [EE * EH];   // encoded edge features
__device__             float g_a   [EE * HH];    // exp(logit), indexed by CSR SLOT
// CSR by destination node (built once per launch)
__device__ int  g_cnt   [NN];
__device__ int  g_wptr  [NN];
__device__ int  g_rowptr[NN + 1];
__device__ int2 g_csr    [EE];   // (orig edge id, src node) per slot
__device__ int  g_csr_dst[EE];   // dst node per slot

typedef unsigned long long u64;

__device__ __forceinline__ float warp_sum(float v) {
#pragma unroll
    for (int o = 16; o; o >>= 1) v += __shfl_xor_sync(0xffffffffu, v, o);
    return v;
}
// ---- packed f32x2 helpers (sm_100a) ----
__device__ __forceinline__ u64 dup2(float v) {
    u64 r; asm("mov.b64 %0, {%1, %1};" : "=l"(r) : "f"(v)); return r;
}
__device__ __forceinline__ u64 ffma2(u64 a, u64 b, u64 c) {
    u64 d; asm("fma.rn.f32x2 %0, %1, %2, %3;" : "=l"(d) : "l"(a), "l"(b), "l"(c));
    return d;
}
__device__ __forceinline__ float2 unpack2(u64 p) {
    float2 r; asm("mov.b64 {%0, %1}, %2;" : "=f"(r.x), "=f"(r.y) : "l"(p));
    return r;
}
__device__ __forceinline__ uint32_t to_tf32(float f) {
    uint32_t t; asm("cvt.rna.tf32.f32 %0, %1;" : "=r"(t) : "f"(f)); return t;
}
__device__ __forceinline__ u64 pack2u(uint32_t lo, uint32_t hi) {
    return ((u64)hi << 32) | (u64)lo;
}
// pack two fp32 into bf16x2 (lo in bits[15:0])
__device__ __forceinline__ uint32_t pack_bf2(float lo, float hi) {
    uint32_t r;
    asm("cvt.rn.bf16x2.f32 %0, %1, %2;" : "=r"(r) : "f"(hi), "f"(lo));
    return r;
}
// unpack bf16x2 -> float2 (shift-based, ALU only)
__device__ __forceinline__ float2 unpack_bf2(uint32_t u) {
    float2 r;
    r.x = __uint_as_float(u << 16);
    r.y = __uint_as_float(u & 0xffff0000u);
    return r;
}

// ---------------- node encoder: x(N,9) -> LN -> relu -> g_h(N,128). 1 warp/node ----
__global__ void node_enc_kernel(const float* __restrict__ x,
                                const float* __restrict__ W,
                                const float* __restrict__ b,
                                const float* __restrict__ g,
                                const float* __restrict__ beta) {
    int warp = (blockIdx.x * blockDim.x + threadIdx.x) >> 5;
    int lane = threadIdx.x & 31;
    if (warp >= NN) return;
    float acc[4];
#pragma unroll
    for (int j = 0; j < 4; j++) acc[j] = b[lane + 32 * j];
#pragma unroll
    for (int k = 0; k < 9; k++) {
        float xv = x[warp * 9 + k];
#pragma unroll
        for (int j = 0; j < 4; j++) acc[j] += xv * W[k * DD + lane + 32 * j];
    }
    float s = 0.f;
#pragma unroll
    for (int j = 0; j < 4; j++) s += acc[j];
    float m = warp_sum(s) * (1.0f / DD);
    float v = 0.f;
#pragma unroll
    for (int j = 0; j < 4; j++) { float d = acc[j] - m; v += d * d; }
    v = warp_sum(v) * (1.0f / DD);
    float rstd = rsqrtf(v + 1e-5f);
#pragma unroll
    for (int j = 0; j < 4; j++) {
        int d = lane + 32 * j;
        float y = (acc[j] - m) * rstd * g[d] + beta[d];
        g_h[warp * DD + d] = fmaxf(y, 0.0f);
    }
}

// ---------------- edge encoder: edge_attr(E,3) -> LN -> relu -> g_ef(E,64) ---------
__global__ void edge_enc_kernel(const float* __restrict__ ea,
                                const float* __restrict__ W,
                                const float* __restrict__ b,
                                const float* __restrict__ g,
                                const float* __restrict__ beta) {
    int warp = (blockIdx.x * blockDim.x + threadIdx.x) >> 5;
    int lane = threadIdx.x & 31;
    if (warp >= EE) return;
    float a0 = b[lane], a1 = b[lane + 32];
#pragma unroll
    for (int k = 0; k < 3; k++) {
        float xv = ea[warp * 3 + k];
        a0 += xv * W[k * EH + lane];
        a1 += xv * W[k * EH + 32 + lane];
    }
    float m = warp_sum(a0 + a1) * (1.0f / EH);
    float d0 = a0 - m, d1 = a1 - m;
    float v = warp_sum(d0 * d0 + d1 * d1) * (1.0f / EH);
    float rstd = rsqrtf(v + 1e-5f);
    float y0 = d0 * rstd * g[lane] + beta[lane];
    float y1 = d1 * rstd * g[lane + 32] + beta[lane + 32];
    g_ef[warp * EH + lane]      = fmaxf(y0, 0.f);
    g_ef[warp * EH + 32 + lane] = fmaxf(y1, 0.f);
}

// ---------------- CSR build (once per launch) --------------------------------------
__global__ void csr_zero_kernel() {
    int i = blockIdx.x * blockDim.x + threadIdx.x;
    if (i < NN) g_cnt[i] = 0;
}
__global__ void csr_count_kernel(const int* __restrict__ ei) {
    int e = blockIdx.x * blockDim.x + threadIdx.x;
    if (e < EE) atomicAdd(&g_cnt[ei[EE + e]], 1);
}
__global__ void csr_scan_kernel() {
    __shared__ int warpsum[32];
    __shared__ int s_total;
    int tid = threadIdx.x, lane = tid & 31, wid = tid >> 5;
    if (tid == 0) { s_total = 0; g_rowptr[0] = 0; }
    __syncthreads();
    for (int base = 0; base < NN; base += 1024) {
        int i = base + tid;
        int v = (i < NN) ? g_cnt[i] : 0;
        int x = v;
#pragma unroll
        for (int o = 1; o < 32; o <<= 1) {
            int t = __shfl_up_sync(0xffffffffu, x, o);
            if (lane >= o) x += t;
        }
        if (lane == 31) warpsum[wid] = x;
        __syncthreads();
        if (wid == 0) {
            int w = warpsum[lane];
#pragma unroll
            for (int o = 1; o < 32; o <<= 1) {
                int t = __shfl_up_sync(0xffffffffu, w, o);
                if (lane >= o) w += t;
            }
            warpsum[lane] = w;
        }
        __syncthreads();
        int incl = s_total + (wid ? warpsum[wid - 1] : 0) + x;
        if (i < NN) {
            g_rowptr[i + 1] = incl;
            g_wptr[i] = incl - v;
        }
        __syncthreads();
        if (tid == 0) s_total += warpsum[31];
        __syncthreads();
    }
}
__global__ void csr_scatter_kernel(const int* __restrict__ ei) {
    int e = blockIdx.x * blockDim.x + threadIdx.x;
    if (e < EE) {
        int d = ei[EE + e];
        int pos = atomicAdd(&g_wptr[d], 1);
        g_csr[pos] = make_int2(e, ei[e]);
        g_csr_dst[pos] = d;
    }
}

// ---------------- xl/xr GEMM: 128x128 tile, 8x8/thread, FFMA2 + bf16 mirror --------
#define TM 128
#define TN 128
#define TK 16
#define LIN_SMEM (2 * TK * TM * 8 + 2 * TK * TN * 4)
__global__ __launch_bounds__(256, 2) void lin_kernel(
    const float* __restrict__ Wl, const float* __restrict__ bl,
    const float* __restrict__ Wr, const float* __restrict__ br) {
    extern __shared__ char smem_raw[];
    u64*   sA2 = (u64*)smem_raw;                         // [2][TK][TM] dup pairs
    float* sB  = (float*)(smem_raw + 2 * TK * TM * 8);   // [2][TK][TN]
    const float* W  = blockIdx.y ? Wr : Wl;
    const float* bv = blockIdx.y ? br : bl;
    float* dst = blockIdx.y ? g_xr : g_xl;
    uint32_t* dsth = blockIdx.y ? g_xrh : g_xlh;
    int m0 = blockIdx.x * TM;
    int tid = threadIdx.x;
    int tn = tid & 15, tm = tid >> 4;

    u64 acc[8][4];
#pragma unroll
    for (int i = 0; i < 8; i++)
#pragma unroll
        for (int j = 0; j < 4; j++) acc[i][j] = 0ull;

    float4 ra[2], rb[2];

#define LDG_AB(kc)                                                              \
    {                                                                           \
        _Pragma("unroll")                                                       \
        for (int r = 0; r < 2; r++) {                                           \
            int idx = tid + r * 256;                                            \
            int m = idx >> 2, kq = (idx & 3) << 2;                              \
            int gm = m0 + m;                                                    \
            ra[r] = make_float4(0.f, 0.f, 0.f, 0.f);                            \
            if (gm < NN)                                                        \
                ra[r] = *(const float4*)&g_h[gm * DD + (kc) * TK + kq];         \
            int k = idx >> 5, nq = (idx & 31) << 2;                             \
            rb[r] = *(const float4*)&W[((kc) * TK + k) * DD + nq];              \
        }                                                                       \
    }
#define STS_AB(buf)                                                             \
    {                                                                           \
        _Pragma("unroll")                                                       \
        for (int r = 0; r < 2; r++) {                                           \
            int idx = tid + r * 256;                                            \
            int m = idx >> 2, kq = (idx & 3) << 2;                              \
            u64* pa = sA2 + (buf) * TK * TM;                                    \
            pa[(kq + 0) * TM + m] = dup2(ra[r].x);                              \
            pa[(kq + 1) * TM + m] = dup2(ra[r].y);                              \
            pa[(kq + 2) * TM + m] = dup2(ra[r].z);                              \
            pa[(kq + 3) * TM + m] = dup2(ra[r].w);                              \
            int k = idx >> 5, nq = (idx & 31) << 2;                             \
            *(float4*)&sB[((buf) * TK + k) * TN + nq] = rb[r];                  \
        }                                                                       \
    }

    LDG_AB(0);
    STS_AB(0);
    __syncthreads();
#pragma unroll
    for (int kc = 0; kc < DD / TK; kc++) {
        int buf = kc & 1;
        if (kc + 1 < DD / TK) LDG_AB(kc + 1);
#pragma unroll
        for (int kk = 0; kk < TK; kk++) {
            const u64* pa = sA2 + (buf * TK + kk) * TM + tm * 8;
            const u64* pb = (const u64*)&sB[(buf * TK + kk) * TN];
            u64 ap[8], bp[4];
#pragma unroll
            for (int i = 0; i < 8; i++) ap[i] = pa[i];
            bp[0] = pb[tn * 2];
            bp[1] = pb[tn * 2 + 1];
            bp[2] = pb[32 + tn * 2];
            bp[3] = pb[32 + tn * 2 + 1];
#pragma unroll
            for (int i = 0; i < 8; i++)
#pragma unroll
                for (int j = 0; j < 4; j++)
                    acc[i][j] = ffma2(ap[i], bp[j], acc[i][j]);
        }
        if (kc + 1 < DD / TK) {
            __syncthreads();
            STS_AB(buf ^ 1);
            __syncthreads();
        }
    }
    // epilogue: fp32 outputs + bf16x2 mirrors
    float4 bias0 = *(const float4*)&bv[tn * 4];
    float4 bias1 = *(const float4*)&bv[64 + tn * 4];
#pragma unroll
    for (int i = 0; i < 8; i++) {
        int gm = m0 + tm * 8 + i;
        if (gm < NN) {
            float2 c0 = unpack2(acc[i][0]);
            float2 c1 = unpack2(acc[i][1]);
            float2 c2 = unpack2(acc[i][2]);
            float2 c3 = unpack2(acc[i][3]);
            float4 o0 = make_float4(c0.x + bias0.x, c0.y + bias0.y,
                                    c1.x + bias0.z, c1.y + bias0.w);
            float4 o1 = make_float4(c2.x + bias1.x, c2.y + bias1.y,
                                    c3.x + bias1.z, c3.y + bias1.w);
            *(float4*)&dst[gm * DD + tn * 4] = o0;
            *(float4*)&dst[gm * DD + 64 + tn * 4] = o1;
            uint2 h0 = make_uint2(pack_bf2(o0.x, o0.y), pack_bf2(o0.z, o0.w));
            uint2 h1 = make_uint2(pack_bf2(o1.x, o1.y), pack_bf2(o1.z, o1.w));
            *(uint2*)&dsth[gm * 64 + tn * 2] = h0;
            *(uint2*)&dsth[gm * 64 + 32 + tn * 2] = h1;
        }
    }
#undef LDG_AB
#undef STS_AB
}

// ---------------- pass A: tf32 TC ee GEMM, paired-u64 frags, bf16 xl/xr gathers ----
#define PA_EDGES 128
#define EFS2 36   // u64 stride per row: 32 pairs + 4 pad
#define PASSA_SMEM (PA_EDGES * EFS2 * 8 + DD * EFS2 * 8 + DD * 4)
__global__ __launch_bounds__(256, 3) void passA_kernel(const float* __restrict__ We,
                                                       const float* __restrict__ att) {
    extern __shared__ char smem_raw[];
    u64*   sEf2 = (u64*)smem_raw;                            // [128 rows][EFS2] pairs
    u64*   sWe2 = (u64*)(smem_raw + PA_EDGES * EFS2 * 8);    // [128 n][EFS2] pairs
    float* sAtt = (float*)(smem_raw + PA_EDGES * EFS2 * 8 + DD * EFS2 * 8);
    __shared__ int sSrc[PA_EDGES], sDst[PA_EDGES];
    int tid = threadIdx.x;
    int eb = blockIdx.x * PA_EDGES;

    if (tid < PA_EDGES) {
        int2 c = g_csr[eb + tid];
        sSrc[tid] = c.y;
        sDst[tid] = g_csr_dst[eb + tid];
    }
    if (tid < DD) sAtt[tid] = att[tid];
    // stage We as paired tf32
    for (int idx = tid; idx < DD * (EH / 8); idx += 256) {
        int n = idx & 127, k0 = idx >> 7;
        float w[8];
#pragma unroll
        for (int j = 0; j < 8; j++) w[j] = We[(k0 * 8 + j) * DD + n];
#pragma unroll
        for (int j = 0; j < 4; j++)
            sWe2[n * EFS2 + k0 * 4 + j] = pack2u(to_tf32(w[j]), to_tf32(w[j + 4]));
    }
    // stage ef tile (gathered by orig edge id) as paired tf32
    for (int idx = tid; idx < PA_EDGES * (EH / 8); idx += 256) {
        int r = idx >> 3, k8 = (idx & 7) << 3;
        int e = g_csr[eb + r].x;
        float4 v0 = *(const float4*)&g_ef[(size_t)e * EH + k8];
        float4 v1 = *(const float4*)&g_ef[(size_t)e * EH + k8 + 4];
        u64* dst = sEf2 + r * EFS2 + (k8 >> 3) * 4;
        dst[0] = pack2u(to_tf32(v0.x), to_tf32(v1.x));
        dst[1] = pack2u(to_tf32(v0.y), to_tf32(v1.y));
        dst[2] = pack2u(to_tf32(v0.z), to_tf32(v1.z));
        dst[3] = pack2u(to_tf32(v0.w), to_tf32(v1.w));
    }
    __syncthreads();

    int lane = tid & 31, wm = tid >> 5;
    int gid = lane >> 2, q = lane & 3;

    int r0 = wm * 16 + gid;
    int r1 = r0 + 8;
    const uint32_t* xl0h = g_xlh + (size_t)sSrc[r0] * 64;
    const uint32_t* xr0h = g_xrh + (size_t)sDst[r0] * 64;
    const uint32_t* xl1h = g_xlh + (size_t)sSrc[r1] * 64;
    const uint32_t* xr1h = g_xrh + (size_t)sDst[r1] * 64;
    const u64* efr0 = sEf2 + r0 * EFS2;
    const u64* efr1 = sEf2 + r1 * EFS2;

    float h0[8], h1[8];
#pragma unroll
    for (int h = 0; h < 8; h++) { h0[h] = 0.f; h1[h] = 0.f; }

#pragma unroll
    for (int half = 0; half < 2; half++) {
        float d[8][4];
#pragma unroll
        for (int n8 = 0; n8 < 8; n8++)
#pragma unroll
            for (int j = 0; j < 4; j++) d[n8][j] = 0.f;

#pragma unroll
        for (int k0 = 0; k0 < 8; k0++) {
            u64 pa0 = efr0[k0 * 4 + q];
            u64 pa1 = efr1[k0 * 4 + q];
            uint32_t a0 = (uint32_t)pa0, a2 = (uint32_t)(pa0 >> 32);
            uint32_t a1 = (uint32_t)pa1, a3 = (uint32_t)(pa1 >> 32);
#pragma unroll
            for (int n8 = 0; n8 < 8; n8++) {
                int n = half * 8 + n8;
                u64 pb = sWe2[(n * 8 + gid) * EFS2 + k0 * 4 + q];
                uint32_t b0 = (uint32_t)pb, b1 = (uint32_t)(pb >> 32);
                asm volatile(
                    "mma.sync.aligned.m16n8k8.row.col.f32.tf32.tf32.f32 "
                    "{%0,%1,%2,%3}, {%4,%5,%6,%7}, {%8,%9}, {%0,%1,%2,%3};"
                    : "+f"(d[n8][0]), "+f"(d[n8][1]), "+f"(d[n8][2]), "+f"(d[n8][3])
                    : "r"(a0), "r"(a1), "r"(a2), "r"(a3), "r"(b0), "r"(b1));
            }
        }
#pragma unroll
        for (int n8 = 0; n8 < 8; n8++) {
            int n = half * 8 + n8;
            int ci = n * 4 + q;            // bf16x2 index of cols (n*8+2q, +1)
            float2 av = *(const float2*)&sAtt[n * 8 + q * 2];
            float2 l0v = unpack_bf2(xl0h[ci]);
            float2 r0v = unpack_bf2(xr0h[ci]);
            float2 l1v = unpack_bf2(xl1h[ci]);
            float2 r1v = unpack_bf2(xr1h[ci]);
            float v00 = d[n8][0] + l0v.x + r0v.x; v00 = v00 > 0.f ? v00 : 0.2f * v00;
            float v01 = d[n8][1] + l0v.y + r0v.y; v01 = v01 > 0.f ? v01 : 0.2f * v01;
            float v10 = d[n8][2] + l1v.x + r1v.x; v10 = v10 > 0.f ? v10 : 0.2f * v10;
            float v11 = d[n8][3] + l1v.y + r1v.y; v11 = v11 > 0.f ? v11 : 0.2f * v11;
            h0[n >> 1] += v00 * av.x + v01 * av.y;
            h1[n >> 1] += v10 * av.x + v11 * av.y;
        }
    }
#pragma unroll
    for (int h = 0; h < 8; h++) {
        h0[h] += __shfl_xor_sync(0xffffffffu, h0[h], 1);
        h0[h] += __shfl_xor_sync(0xffffffffu, h0[h], 2);
        h1[h] += __shfl_xor_sync(0xffffffffu, h1[h], 1);
        h1[h] += __shfl_xor_sync(0xffffffffu, h1[h], 2);
    }
    size_t p0 = (size_t)(eb + r0) * HH;
    size_t p1 = (size_t)(eb + r1) * HH;
    g_a[p0 + 2 * q]     = expf(h0[2 * q]);
    g_a[p0 + 2 * q + 1] = expf(h0[2 * q + 1]);
    g_a[p1 + 2 * q]     = expf(h1[2 * q]);
    g_a[p1 + 2 * q + 1] = expf(h1[2 * q + 1]);
}

// ---------------- pass B: per-dst gather (no atomics) + fused residual+LN+relu -----
__global__ void passB_kernel(const float* __restrict__ cb,
                             const float* __restrict__ g,
                             const float* __restrict__ beta) {
    int node = (blockIdx.x * blockDim.x + threadIdx.x) >> 5;
    int lane = threadIdx.x & 31;
    if (node >= NN) return;
    int start = g_rowptr[node], end = g_rowptr[node + 1];

    float s = 0.f;
    for (int p0 = start; p0 < end; p0 += 4) {
        int p = p0 + (lane >> 3);
        if (p < end) s += g_a[(size_t)p * HH + (lane & 7)];
    }
    s += __shfl_xor_sync(0xffffffffu, s, 8);
    s += __shfl_xor_sync(0xffffffffu, s, 16);
    float sh = __shfl_sync(0xffffffffu, s, lane >> 2);
    float rinv = 1.0f / (sh + 1e-16f);

    int head = lane >> 2;
    float4 acc = make_float4(0.f, 0.f, 0.f, 0.f);
    int p = start;
    for (; p + 4 <= end; p += 4) {
        int s0 = g_csr[p].y,     s1 = g_csr[p + 1].y;
        int s2 = g_csr[p + 2].y, s3 = g_csr[p + 3].y;
        float a0 = g_a[(size_t)(p)     * HH + head];
        float a1 = g_a[(size_t)(p + 1) * HH + head];
        float a2 = g_a[(size_t)(p + 2) * HH + head];
        float a3 = g_a[(size_t)(p + 3) * HH + head];
        float4 x0 = *(const float4*)&g_xl[(size_t)s0 * DD + 4 * lane];
        float4 x1 = *(const float4*)&g_xl[(size_t)s1 * DD + 4 * lane];
        float4 x2 = *(const float4*)&g_xl[(size_t)s2 * DD + 4 * lane];
        float4 x3 = *(const float4*)&g_xl[(size_t)s3 * DD + 4 * lane];
        acc.x += a0 * x0.x + a1 * x1.x + a2 * x2.x + a3 * x3.x;
        acc.y += a0 * x0.y + a1 * x1.y + a2 * x2.y + a3 * x3.y;
        acc.z += a0 * x0.z + a1 * x1.z + a2 * x2.z + a3 * x3.z;
        acc.w += a0 * x0.w + a1 * x1.w + a2 * x2.w + a3 * x3.w;
    }
    for (; p < end; p++) {
        int sn = g_csr[p].y;
        float al = g_a[(size_t)p * HH + head];
        float4 xv = *(const float4*)&g_xl[(size_t)sn * DD + 4 * lane];
        acc.x += al * xv.x; acc.y += al * xv.y;
        acc.z += al * xv.z; acc.w += al * xv.w;
    }
    acc.x *= rinv; acc.y *= rinv; acc.z *= rinv; acc.w *= rinv;

    int d0 = 4 * lane;
    float4 hv = *(const float4*)&g_h[node * DD + d0];
    float4 cv = *(const float4*)&cb[d0];
    float a0 = acc.x + cv.x + hv.x;
    float a1 = acc.y + cv.y + hv.y;
    float a2 = acc.z + cv.z + hv.z;
    float a3 = acc.w + cv.w + hv.w;
    float m = warp_sum(a0 + a1 + a2 + a3) * (1.0f / DD);
    float e0d = a0 - m, e1d = a1 - m, e2d = a2 - m, e3d = a3 - m;
    float v = warp_sum(e0d * e0d + e1d * e1d + e2d * e2d + e3d * e3d) * (1.0f / DD);
    float rstd = rsqrtf(v + 1e-5f);
    float4 gv = *(const float4*)&g[d0];
    float4 bv = *(const float4*)&beta[d0];
    float4 o;
    o.x = fmaxf(e0d * rstd * gv.x + bv.x, 0.f);
    o.y = fmaxf(e1d * rstd * gv.y + bv.y, 0.f);
    o.z = fmaxf(e2d * rstd * gv.z + bv.z, 0.f);
    o.w = fmaxf(e3d * rstd * gv.w + bv.w, 0.f);
    *(float4*)&g_h[node * DD + d0] = o;
}

// ---------------- head: relu(h@W1+b1) @ W2 -> sigmoid. 1 warp/node -----------------
__global__ void head_kernel(float* __restrict__ out,
                            const float* __restrict__ W1, const float* __restrict__ b1,
                            const float* __restrict__ W2, const float* __restrict__ b2) {
    int warp = (blockIdx.x * blockDim.x + threadIdx.x) >> 5;
    int lane = threadIdx.x & 31;
    if (warp >= NN) return;
    float hr[4];
#pragma unroll
    for (int q = 0; q < 4; q++) hr[q] = g_h[warp * DD + q * 32 + lane];
    float z0 = b1[lane], z1 = b1[lane + 32];
#pragma unroll
    for (int q = 0; q < 4; q++) {
#pragma unroll 8
        for (int kk = 0; kk < 32; kk++) {
            float hk = __shfl_sync(0xffffffffu, hr[q], kk);
            int k = q * 32 + kk;
            z0 += hk * W1[k * 64 + lane];
            z1 += hk * W1[k * 64 + 32 + lane];
        }
    }
    z0 = fmaxf(z0, 0.f);
    z1 = fmaxf(z1, 0.f);
    float p = z0 * W2[lane] + z1 * W2[lane + 32];
    p = warp_sum(p);
    if (lane == 0) out[warp] = 1.0f / (1.0f + expf(-(p + b2[0])));
}

// ---------------- launch ----------------------------------------------------------
extern "C" void kernel_launch(void* const* d_in, const int* in_sizes, int n_in,
                              void* d_out, int out_size) {
    const float* x    = (const float*)d_in[0];
    const int*   ei   = (const int*)  d_in[1];
    const float* ea   = (const float*)d_in[2];
    const float* neW  = (const float*)d_in[3];
    const float* neb  = (const float*)d_in[4];
    const float* neg  = (const float*)d_in[5];
    const float* nebt = (const float*)d_in[6];
    const float* eeW  = (const float*)d_in[7];
    const float* eeb  = (const float*)d_in[8];
    const float* eeg  = (const float*)d_in[9];
    const float* eebt = (const float*)d_in[10];
    const float* Wl   = (const float*)d_in[11];
    const float* bl   = (const float*)d_in[12];
    const float* Wr   = (const float*)d_in[13];
    const float* br   = (const float*)d_in[14];
    const float* We   = (const float*)d_in[15];
    const float* att  = (const float*)d_in[16];
    const float* cb   = (const float*)d_in[17];
    const float* lng  = (const float*)d_in[18];
    const float* lnb  = (const float*)d_in[19];
    const float* W1   = (const float*)d_in[20];
    const float* b1   = (const float*)d_in[21];
    const float* W2   = (const float*)d_in[22];
    const float* b2   = (const float*)d_in[23];
    float* out = (float*)d_out;

    cudaFuncSetAttribute(lin_kernel, cudaFuncAttributeMaxDynamicSharedMemorySize,
                         LIN_SMEM);
    cudaFuncSetAttribute(passA_kernel, cudaFuncAttributeMaxDynamicSharedMemorySize,
                         PASSA_SMEM);

    dim3 lin_grid((NN + TM - 1) / TM, 2);
    int passa_grid = EE / PA_EDGES;

    node_enc_kernel<<<NN / 8, 256>>>(x, neW, neb, neg, nebt);                    // 0
    csr_zero_kernel<<<(NN + 255) / 256, 256>>>();                                // 1
    csr_count_kernel<<<(EE + 255) / 256, 256>>>(ei);                             // 2
    lin_kernel<<<lin_grid, 256, LIN_SMEM>>>(Wl, bl, Wr, br);                     // 3 (profiled; control)
    csr_scan_kernel<<<1, 1024>>>();                                              // 4
    csr_scatter_kernel<<<(EE + 255) / 256, 256>>>(ei);                           // 5
    edge_enc_kernel<<<EE / 8, 256>>>(ea, eeW, eeb, eeg, eebt);                   // 6

    for (int l = 0; l < LL; l++) {
        if (l > 0)
            lin_kernel<<<lin_grid, 256, LIN_SMEM>>>(Wl + l * DD * DD, bl + l * DD,
                                                    Wr + l * DD * DD, br + l * DD);
        passA_kernel<<<passa_grid, 256, PASSA_SMEM>>>(We + l * EH * DD,
                                                      att + l * HH * CC);
        passB_kernel<<<(NN * 32 + 255) / 256, 256>>>(cb + l * DD, lng + l * DD,
                                                     lnb + l * DD);
    }
    head_kernel<<<NN / 8, 256>>>(out, W1, b1, W2, b2);
}

// round 11
// speedup vs baseline: 1.2544x; 1.1231x over previous
#include <cuda_runtime.h>
#include <math.h>
#include <stdint.h>

#define NN 50000
#define EE 400000
#define DD 128
#define HH 8
#define CC 16
#define EH 64
#define LL 6

static_assert(EE % 128 == 0, "edge tiling");
static_assert(NN % 8 == 0, "node tiling");

// ---------------- device scratch (static; no allocations allowed) ----------------
__device__ __align__(16) float g_h  [NN * DD];   // node features
__device__ __align__(16) float g_xl [NN * DD];   // lin_l output (fp32)
__device__ __align__(16) float g_xr [NN * DD];   // lin_r output (fp32)
__device__ __align__(8) uint32_t g_xlh[NN * 64]; // bf16x2 mirror of xl (for passA)
__device__ __align__(8) uint32_t g_xrh[NN * 64]; // bf16x2 mirror of xr (for passA)
__device__ __align__(16) float g_ef [EE * EH];   // encoded edge features
__device__             float g_a   [EE * HH];    // exp(logit), indexed by CSR SLOT
// CSR by destination node (built once per launch)
__device__ int  g_cnt   [NN];
__device__ int  g_wptr  [NN];
__device__ int  g_rowptr[NN + 1];
__device__ int2 g_csr    [EE];   // (orig edge id, src node) per slot
__device__ int  g_csr_dst[EE];   // dst node per slot

typedef unsigned long long u64;

__device__ __forceinline__ float warp_sum(float v) {
#pragma unroll
    for (int o = 16; o; o >>= 1) v += __shfl_xor_sync(0xffffffffu, v, o);
    return v;
}
__device__ __forceinline__ uint32_t to_tf32(float f) {
    uint32_t t; asm("cvt.rna.tf32.f32 %0, %1;" : "=r"(t) : "f"(f)); return t;
}
__device__ __forceinline__ u64 pack2u(uint32_t lo, uint32_t hi) {
    return ((u64)hi << 32) | (u64)lo;
}
__device__ __forceinline__ uint32_t pack_bf2(float lo, float hi) {
    uint32_t r;
    asm("cvt.rn.bf16x2.f32 %0, %1, %2;" : "=r"(r) : "f"(hi), "f"(lo));
    return r;
}
__device__ __forceinline__ float2 unpack_bf2(uint32_t u) {
    float2 r;
    r.x = __uint_as_float(u << 16);
    r.y = __uint_as_float(u & 0xffff0000u);
    return r;
}

// ---------------- node encoder: x(N,9) -> LN -> relu -> g_h(N,128). 1 warp/node ----
__global__ void node_enc_kernel(const float* __restrict__ x,
                                const float* __restrict__ W,
                                const float* __restrict__ b,
                                const float* __restrict__ g,
                                const float* __restrict__ beta) {
    int warp = (blockIdx.x * blockDim.x + threadIdx.x) >> 5;
    int lane = threadIdx.x & 31;
    if (warp >= NN) return;
    float acc[4];
#pragma unroll
    for (int j = 0; j < 4; j++) acc[j] = b[lane + 32 * j];
#pragma unroll
    for (int k = 0; k < 9; k++) {
        float xv = x[warp * 9 + k];
#pragma unroll
        for (int j = 0; j < 4; j++) acc[j] += xv * W[k * DD + lane + 32 * j];
    }
    float s = 0.f;
#pragma unroll
    for (int j = 0; j < 4; j++) s += acc[j];
    float m = warp_sum(s) * (1.0f / DD);
    float v = 0.f;
#pragma unroll
    for (int j = 0; j < 4; j++) { float d = acc[j] - m; v += d * d; }
    v = warp_sum(v) * (1.0f / DD);
    float rstd = rsqrtf(v + 1e-5f);
#pragma unroll
    for (int j = 0; j < 4; j++) {
        int d = lane + 32 * j;
        float y = (acc[j] - m) * rstd * g[d] + beta[d];
        g_h[warp * DD + d] = fmaxf(y, 0.0f);
    }
}

// ---------------- edge encoder: edge_attr(E,3) -> LN -> relu -> g_ef(E,64) ---------
__global__ void edge_enc_kernel(const float* __restrict__ ea,
                                const float* __restrict__ W,
                                const float* __restrict__ b,
                                const float* __restrict__ g,
                                const float* __restrict__ beta) {
    int warp = (blockIdx.x * blockDim.x + threadIdx.x) >> 5;
    int lane = threadIdx.x & 31;
    if (warp >= EE) return;
    float a0 = b[lane], a1 = b[lane + 32];
#pragma unroll
    for (int k = 0; k < 3; k++) {
        float xv = ea[warp * 3 + k];
        a0 += xv * W[k * EH + lane];
        a1 += xv * W[k * EH + 32 + lane];
    }
    float m = warp_sum(a0 + a1) * (1.0f / EH);
    float d0 = a0 - m, d1 = a1 - m;
    float v = warp_sum(d0 * d0 + d1 * d1) * (1.0f / EH);
    float rstd = rsqrtf(v + 1e-5f);
    float y0 = d0 * rstd * g[lane] + beta[lane];
    float y1 = d1 * rstd * g[lane + 32] + beta[lane + 32];
    g_ef[warp * EH + lane]      = fmaxf(y0, 0.f);
    g_ef[warp * EH + 32 + lane] = fmaxf(y1, 0.f);
}

// ---------------- CSR build (once per launch) --------------------------------------
__global__ void csr_zero_kernel() {
    int i = blockIdx.x * blockDim.x + threadIdx.x;
    if (i < NN) g_cnt[i] = 0;
}
__global__ void csr_count_kernel(const int* __restrict__ ei) {
    int e = blockIdx.x * blockDim.x + threadIdx.x;
    if (e < EE) atomicAdd(&g_cnt[ei[EE + e]], 1);
}
__global__ void csr_scan_kernel() {
    __shared__ int warpsum[32];
    __shared__ int s_total;
    int tid = threadIdx.x, lane = tid & 31, wid = tid >> 5;
    if (tid == 0) { s_total = 0; g_rowptr[0] = 0; }
    __syncthreads();
    for (int base = 0; base < NN; base += 1024) {
        int i = base + tid;
        int v = (i < NN) ? g_cnt[i] : 0;
        int x = v;
#pragma unroll
        for (int o = 1; o < 32; o <<= 1) {
            int t = __shfl_up_sync(0xffffffffu, x, o);
            if (lane >= o) x += t;
        }
        if (lane == 31) warpsum[wid] = x;
        __syncthreads();
        if (wid == 0) {
            int w = warpsum[lane];
#pragma unroll
            for (int o = 1; o < 32; o <<= 1) {
                int t = __shfl_up_sync(0xffffffffu, w, o);
                if (lane >= o) w += t;
            }
            warpsum[lane] = w;
        }
        __syncthreads();
        int incl = s_total + (wid ? warpsum[wid - 1] : 0) + x;
        if (i < NN) {
            g_rowptr[i + 1] = incl;
            g_wptr[i] = incl - v;
        }
        __syncthreads();
        if (tid == 0) s_total += warpsum[31];
        __syncthreads();
    }
}
__global__ void csr_scatter_kernel(const int* __restrict__ ei) {
    int e = blockIdx.x * blockDim.x + threadIdx.x;
    if (e < EE) {
        int d = ei[EE + e];
        int pos = atomicAdd(&g_wptr[d], 1);
        g_csr[pos] = make_int2(e, ei[e]);
        g_csr_dst[pos] = d;
    }
}

// ---------------- xl/xr GEMM: tf32 tensor cores, 64 rows/block, K=128 --------------
// 8 warps: warp wm covers rows [(wm&3)*16, +16) x cols [(wm>>2)*64, +64).
// Paired-u64 (k, k+4) fragment layout identical to passA (proven conflict-free).
#define LIN_ROWS 64
#define LKS 68   // u64 stride per row: 64 pairs (K=128) + 4 pad
#define LIN_SMEM (LIN_ROWS * LKS * 8 + DD * LKS * 8)
__global__ __launch_bounds__(256, 2) void lin_kernel(
    const float* __restrict__ Wl, const float* __restrict__ bl,
    const float* __restrict__ Wr, const float* __restrict__ br) {
    extern __shared__ char smem_raw[];
    u64* sA = (u64*)smem_raw;                          // [64 rows][LKS] pairs
    u64* sW = (u64*)(smem_raw + LIN_ROWS * LKS * 8);   // [128 n][LKS] pairs
    const float* W  = blockIdx.y ? Wr : Wl;
    const float* bv = blockIdx.y ? br : bl;
    float* dst = blockIdx.y ? g_xr : g_xl;
    uint32_t* dsth = blockIdx.y ? g_xrh : g_xlh;
    int m0 = blockIdx.x * LIN_ROWS;
    int tid = threadIdx.x;

    // stage A (h rows) as paired tf32: 64 rows x 16 k8-groups
    for (int idx = tid; idx < LIN_ROWS * (DD / 8); idx += 256) {
        int r = idx >> 4, k8 = (idx & 15) << 3;
        int gm = m0 + r;
        float4 v0 = make_float4(0.f, 0.f, 0.f, 0.f), v1 = v0;
        if (gm < NN) {
            v0 = *(const float4*)&g_h[(size_t)gm * DD + k8];
            v1 = *(const float4*)&g_h[(size_t)gm * DD + k8 + 4];
        }
        u64* d = sA + r * LKS + (k8 >> 3) * 4;
        d[0] = pack2u(to_tf32(v0.x), to_tf32(v1.x));
        d[1] = pack2u(to_tf32(v0.y), to_tf32(v1.y));
        d[2] = pack2u(to_tf32(v0.z), to_tf32(v1.z));
        d[3] = pack2u(to_tf32(v0.w), to_tf32(v1.w));
    }
    // stage W as paired tf32: 128 n x 16 k0-groups (column gather)
    for (int idx = tid; idx < DD * (DD / 8); idx += 256) {
        int n = idx & 127, k0 = idx >> 7;
        float w[8];
#pragma unroll
        for (int j = 0; j < 8; j++) w[j] = W[(k0 * 8 + j) * DD + n];
#pragma unroll
        for (int j = 0; j < 4; j++)
            sW[n * LKS + k0 * 4 + j] = pack2u(to_tf32(w[j]), to_tf32(w[j + 4]));
    }
    __syncthreads();

    int lane = tid & 31, wm = tid >> 5;
    int gid = lane >> 2, q = lane & 3;
    int row_base = (wm & 3) * 16;
    int n_base = (wm >> 2) * 64;
    int r0 = row_base + gid, r1 = r0 + 8;
    const u64* ar0 = sA + r0 * LKS;
    const u64* ar1 = sA + r1 * LKS;

    float d[8][4];
#pragma unroll
    for (int n8 = 0; n8 < 8; n8++)
#pragma unroll
        for (int j = 0; j < 4; j++) d[n8][j] = 0.f;

#pragma unroll
    for (int k0 = 0; k0 < 16; k0++) {
        u64 pa0 = ar0[k0 * 4 + q];
        u64 pa1 = ar1[k0 * 4 + q];
        uint32_t a0 = (uint32_t)pa0, a2 = (uint32_t)(pa0 >> 32);
        uint32_t a1 = (uint32_t)pa1, a3 = (uint32_t)(pa1 >> 32);
#pragma unroll
        for (int n8 = 0; n8 < 8; n8++) {
            u64 pb = sW[(n_base + n8 * 8 + gid) * LKS + k0 * 4 + q];
            uint32_t b0 = (uint32_t)pb, b1 = (uint32_t)(pb >> 32);
            asm volatile(
                "mma.sync.aligned.m16n8k8.row.col.f32.tf32.tf32.f32 "
                "{%0,%1,%2,%3}, {%4,%5,%6,%7}, {%8,%9}, {%0,%1,%2,%3};"
                : "+f"(d[n8][0]), "+f"(d[n8][1]), "+f"(d[n8][2]), "+f"(d[n8][3])
                : "r"(a0), "r"(a1), "r"(a2), "r"(a3), "r"(b0), "r"(b1));
        }
    }

    // epilogue: bias + fp32 store + bf16x2 mirror
    int gm0 = m0 + r0, gm1 = m0 + r1;
#pragma unroll
    for (int n8 = 0; n8 < 8; n8++) {
        int c = n_base + n8 * 8 + 2 * q;
        float2 bb = *(const float2*)&bv[c];
        if (gm0 < NN) {
            float2 o = make_float2(d[n8][0] + bb.x, d[n8][1] + bb.y);
            *(float2*)&dst[(size_t)gm0 * DD + c] = o;
            dsth[(size_t)gm0 * 64 + (c >> 1)] = pack_bf2(o.x, o.y);
        }
        if (gm1 < NN) {
            float2 o = make_float2(d[n8][2] + bb.x, d[n8][3] + bb.y);
            *(float2*)&dst[(size_t)gm1 * DD + c] = o;
            dsth[(size_t)gm1 * 64 + (c >> 1)] = pack_bf2(o.x, o.y);
        }
    }
}

// ---------------- pass A: tf32 TC ee GEMM, paired-u64 frags, bf16 xl/xr gathers ----
#define PA_EDGES 128
#define EFS2 36   // u64 stride per row: 32 pairs + 4 pad
#define PASSA_SMEM (PA_EDGES * EFS2 * 8 + DD * EFS2 * 8 + DD * 4)
__global__ __launch_bounds__(256, 3) void passA_kernel(const float* __restrict__ We,
                                                       const float* __restrict__ att) {
    extern __shared__ char smem_raw[];
    u64*   sEf2 = (u64*)smem_raw;                            // [128 rows][EFS2] pairs
    u64*   sWe2 = (u64*)(smem_raw + PA_EDGES * EFS2 * 8);    // [128 n][EFS2] pairs
    float* sAtt = (float*)(smem_raw + PA_EDGES * EFS2 * 8 + DD * EFS2 * 8);
    __shared__ int sSrc[PA_EDGES], sDst[PA_EDGES];
    int tid = threadIdx.x;
    int eb = blockIdx.x * PA_EDGES;

    if (tid < PA_EDGES) {
        int2 c = g_csr[eb + tid];
        sSrc[tid] = c.y;
        sDst[tid] = g_csr_dst[eb + tid];
    }
    if (tid < DD) sAtt[tid] = att[tid];
    for (int idx = tid; idx < DD * (EH / 8); idx += 256) {
        int n = idx & 127, k0 = idx >> 7;
        float w[8];
#pragma unroll
        for (int j = 0; j < 8; j++) w[j] = We[(k0 * 8 + j) * DD + n];
#pragma unroll
        for (int j = 0; j < 4; j++)
            sWe2[n * EFS2 + k0 * 4 + j] = pack2u(to_tf32(w[j]), to_tf32(w[j + 4]));
    }
    for (int idx = tid; idx < PA_EDGES * (EH / 8); idx += 256) {
        int r = idx >> 3, k8 = (idx & 7) << 3;
        int e = g_csr[eb + r].x;
        float4 v0 = *(const float4*)&g_ef[(size_t)e * EH + k8];
        float4 v1 = *(const float4*)&g_ef[(size_t)e * EH + k8 + 4];
        u64* dstp = sEf2 + r * EFS2 + (k8 >> 3) * 4;
        dstp[0] = pack2u(to_tf32(v0.x), to_tf32(v1.x));
        dstp[1] = pack2u(to_tf32(v0.y), to_tf32(v1.y));
        dstp[2] = pack2u(to_tf32(v0.z), to_tf32(v1.z));
        dstp[3] = pack2u(to_tf32(v0.w), to_tf32(v1.w));
    }
    __syncthreads();

    int lane = tid & 31, wm = tid >> 5;
    int gid = lane >> 2, q = lane & 3;

    int r0 = wm * 16 + gid;
    int r1 = r0 + 8;
    const uint32_t* xl0h = g_xlh + (size_t)sSrc[r0] * 64;
    const uint32_t* xr0h = g_xrh + (size_t)sDst[r0] * 64;
    const uint32_t* xl1h = g_xlh + (size_t)sSrc[r1] * 64;
    const uint32_t* xr1h = g_xrh + (size_t)sDst[r1] * 64;
    const u64* efr0 = sEf2 + r0 * EFS2;
    const u64* efr1 = sEf2 + r1 * EFS2;

    float h0[8], h1[8];
#pragma unroll
    for (int h = 0; h < 8; h++) { h0[h] = 0.f; h1[h] = 0.f; }

#pragma unroll
    for (int half = 0; half < 2; half++) {
        float d[8][4];
#pragma unroll
        for (int n8 = 0; n8 < 8; n8++)
#pragma unroll
            for (int j = 0; j < 4; j++) d[n8][j] = 0.f;

#pragma unroll
        for (int k0 = 0; k0 < 8; k0++) {
            u64 pa0 = efr0[k0 * 4 + q];
            u64 pa1 = efr1[k0 * 4 + q];
            uint32_t a0 = (uint32_t)pa0, a2 = (uint32_t)(pa0 >> 32);
            uint32_t a1 = (uint32_t)pa1, a3 = (uint32_t)(pa1 >> 32);
#pragma unroll
            for (int n8 = 0; n8 < 8; n8++) {
                int n = half * 8 + n8;
                u64 pb = sWe2[(n * 8 + gid) * EFS2 + k0 * 4 + q];
                uint32_t b0 = (uint32_t)pb, b1 = (uint32_t)(pb >> 32);
                asm volatile(
                    "mma.sync.aligned.m16n8k8.row.col.f32.tf32.tf32.f32 "
                    "{%0,%1,%2,%3}, {%4,%5,%6,%7}, {%8,%9}, {%0,%1,%2,%3};"
                    : "+f"(d[n8][0]), "+f"(d[n8][1]), "+f"(d[n8][2]), "+f"(d[n8][3])
                    : "r"(a0), "r"(a1), "r"(a2), "r"(a3), "r"(b0), "r"(b1));
            }
        }
#pragma unroll
        for (int n8 = 0; n8 < 8; n8++) {
            int n = half * 8 + n8;
            int ci = n * 4 + q;
            float2 av = *(const float2*)&sAtt[n * 8 + q * 2];
            float2 l0v = unpack_bf2(xl0h[ci]);
            float2 r0v = unpack_bf2(xr0h[ci]);
            float2 l1v = unpack_bf2(xl1h[ci]);
            float2 r1v = unpack_bf2(xr1h[ci]);
            float v00 = d[n8][0] + l0v.x + r0v.x; v00 = v00 > 0.f ? v00 : 0.2f * v00;
            float v01 = d[n8][1] + l0v.y + r0v.y; v01 = v01 > 0.f ? v01 : 0.2f * v01;
            float v10 = d[n8][2] + l1v.x + r1v.x; v10 = v10 > 0.f ? v10 : 0.2f * v10;
            float v11 = d[n8][3] + l1v.y + r1v.y; v11 = v11 > 0.f ? v11 : 0.2f * v11;
            h0[n >> 1] += v00 * av.x + v01 * av.y;
            h1[n >> 1] += v10 * av.x + v11 * av.y;
        }
    }
#pragma unroll
    for (int h = 0; h < 8; h++) {
        h0[h] += __shfl_xor_sync(0xffffffffu, h0[h], 1);
        h0[h] += __shfl_xor_sync(0xffffffffu, h0[h], 2);
        h1[h] += __shfl_xor_sync(0xffffffffu, h1[h], 1);
        h1[h] += __shfl_xor_sync(0xffffffffu, h1[h], 2);
    }
    size_t p0 = (size_t)(eb + r0) * HH;
    size_t p1 = (size_t)(eb + r1) * HH;
    g_a[p0 + 2 * q]     = expf(h0[2 * q]);
    g_a[p0 + 2 * q + 1] = expf(h0[2 * q + 1]);
    g_a[p1 + 2 * q]     = expf(h1[2 * q]);
    g_a[p1 + 2 * q + 1] = expf(h1[2 * q + 1]);
}

// ---------------- pass B: per-dst gather (no atomics) + fused residual+LN+relu -----
__global__ void passB_kernel(const float* __restrict__ cb,
                             const float* __restrict__ g,
                             const float* __restrict__ beta) {
    int node = (blockIdx.x * blockDim.x + threadIdx.x) >> 5;
    int lane = threadIdx.x & 31;
    if (node >= NN) return;
    int start = g_rowptr[node], end = g_rowptr[node + 1];

    float s = 0.f;
    for (int p0 = start; p0 < end; p0 += 4) {
        int p = p0 + (lane >> 3);
        if (p < end) s += g_a[(size_t)p * HH + (lane & 7)];
    }
    s += __shfl_xor_sync(0xffffffffu, s, 8);
    s += __shfl_xor_sync(0xffffffffu, s, 16);
    float sh = __shfl_sync(0xffffffffu, s, lane >> 2);
    float rinv = 1.0f / (sh + 1e-16f);

    int head = lane >> 2;
    float4 acc = make_float4(0.f, 0.f, 0.f, 0.f);
    int p = start;
    for (; p + 4 <= end; p += 4) {
        int s0 = g_csr[p].y,     s1 = g_csr[p + 1].y;
        int s2 = g_csr[p + 2].y, s3 = g_csr[p + 3].y;
        float a0 = g_a[(size_t)(p)     * HH + head];
        float a1 = g_a[(size_t)(p + 1) * HH + head];
        float a2 = g_a[(size_t)(p + 2) * HH + head];
        float a3 = g_a[(size_t)(p + 3) * HH + head];
        float4 x0 = *(const float4*)&g_xl[(size_t)s0 * DD + 4 * lane];
        float4 x1 = *(const float4*)&g_xl[(size_t)s1 * DD + 4 * lane];
        float4 x2 = *(const float4*)&g_xl[(size_t)s2 * DD + 4 * lane];
        float4 x3 = *(const float4*)&g_xl[(size_t)s3 * DD + 4 * lane];
        acc.x += a0 * x0.x + a1 * x1.x + a2 * x2.x + a3 * x3.x;
        acc.y += a0 * x0.y + a1 * x1.y + a2 * x2.y + a3 * x3.y;
        acc.z += a0 * x0.z + a1 * x1.z + a2 * x2.z + a3 * x3.z;
        acc.w += a0 * x0.w + a1 * x1.w + a2 * x2.w + a3 * x3.w;
    }
    for (; p < end; p++) {
        int sn = g_csr[p].y;
        float al = g_a[(size_t)p * HH + head];
        float4 xv = *(const float4*)&g_xl[(size_t)sn * DD + 4 * lane];
        acc.x += al * xv.x; acc.y += al * xv.y;
        acc.z += al * xv.z; acc.w += al * xv.w;
    }
    acc.x *= rinv; acc.y *= rinv; acc.z *= rinv; acc.w *= rinv;

    int d0 = 4 * lane;
    float4 hv = *(const float4*)&g_h[node * DD + d0];
    float4 cv = *(const float4*)&cb[d0];
    float a0 = acc.x + cv.x + hv.x;
    float a1 = acc.y + cv.y + hv.y;
    float a2 = acc.z + cv.z + hv.z;
    float a3 = acc.w + cv.w + hv.w;
    float m = warp_sum(a0 + a1 + a2 + a3) * (1.0f / DD);
    float e0d = a0 - m, e1d = a1 - m, e2d = a2 - m, e3d = a3 - m;
    float v = warp_sum(e0d * e0d + e1d * e1d + e2d * e2d + e3d * e3d) * (1.0f / DD);
    float rstd = rsqrtf(v + 1e-5f);
    float4 gv = *(const float4*)&g[d0];
    float4 bv = *(const float4*)&beta[d0];
    float4 o;
    o.x = fmaxf(e0d * rstd * gv.x + bv.x, 0.f);
    o.y = fmaxf(e1d * rstd * gv.y + bv.y, 0.f);
    o.z = fmaxf(e2d * rstd * gv.z + bv.z, 0.f);
    o.w = fmaxf(e3d * rstd * gv.w + bv.w, 0.f);
    *(float4*)&g_h[node * DD + d0] = o;
}

// ---------------- head: relu(h@W1+b1) @ W2 -> sigmoid. 1 warp/node -----------------
__global__ void head_kernel(float* __restrict__ out,
                            const float* __restrict__ W1, const float* __restrict__ b1,
                            const float* __restrict__ W2, const float* __restrict__ b2) {
    int warp = (blockIdx.x * blockDim.x + threadIdx.x) >> 5;
    int lane = threadIdx.x & 31;
    if (warp >= NN) return;
    float hr[4];
#pragma unroll
    for (int q = 0; q < 4; q++) hr[q] = g_h[warp * DD + q * 32 + lane];
    float z0 = b1[lane], z1 = b1[lane + 32];
#pragma unroll
    for (int q = 0; q < 4; q++) {
#pragma unroll 8
        for (int kk = 0; kk < 32; kk++) {
            float hk = __shfl_sync(0xffffffffu, hr[q], kk);
            int k = q * 32 + kk;
            z0 += hk * W1[k * 64 + lane];
            z1 += hk * W1[k * 64 + 32 + lane];
        }
    }
    z0 = fmaxf(z0, 0.f);
    z1 = fmaxf(z1, 0.f);
    float p = z0 * W2[lane] + z1 * W2[lane + 32];
    p = warp_sum(p);
    if (lane == 0) out[warp] = 1.0f / (1.0f + expf(-(p + b2[0])));
}

// ---------------- launch ----------------------------------------------------------
extern "C" void kernel_launch(void* const* d_in, const int* in_sizes, int n_in,
                              void* d_out, int out_size) {
    const float* x    = (const float*)d_in[0];
    const int*   ei   = (const int*)  d_in[1];
    const float* ea   = (const float*)d_in[2];
    const float* neW  = (const float*)d_in[3];
    const float* neb  = (const float*)d_in[4];
    const float* neg  = (const float*)d_in[5];
    const float* nebt = (const float*)d_in[6];
    const float* eeW  = (const float*)d_in[7];
    const float* eeb  = (const float*)d_in[8];
    const float* eeg  = (const float*)d_in[9];
    const float* eebt = (const float*)d_in[10];
    const float* Wl   = (const float*)d_in[11];
    const float* bl   = (const float*)d_in[12];
    const float* Wr   = (const float*)d_in[13];
    const float* br   = (const float*)d_in[14];
    const float* We   = (const float*)d_in[15];
    const float* att  = (const float*)d_in[16];
    const float* cb   = (const float*)d_in[17];
    const float* lng  = (const float*)d_in[18];
    const float* lnb  = (const float*)d_in[19];
    const float* W1   = (const float*)d_in[20];
    const float* b1   = (const float*)d_in[21];
    const float* W2   = (const float*)d_in[22];
    const float* b2   = (const float*)d_in[23];
    float* out = (float*)d_out;

    cudaFuncSetAttribute(lin_kernel, cudaFuncAttributeMaxDynamicSharedMemorySize,
                         LIN_SMEM);
    cudaFuncSetAttribute(passA_kernel, cudaFuncAttributeMaxDynamicSharedMemorySize,
                         PASSA_SMEM);

    dim3 lin_grid((NN + LIN_ROWS - 1) / LIN_ROWS, 2);
    int passa_grid = EE / PA_EDGES;

    node_enc_kernel<<<NN / 8, 256>>>(x, neW, neb, neg, nebt);                    // 0
    csr_zero_kernel<<<(NN + 255) / 256, 256>>>();                                // 1
    csr_count_kernel<<<(EE + 255) / 256, 256>>>(ei);                             // 2
    lin_kernel<<<lin_grid, 256, LIN_SMEM>>>(Wl, bl, Wr, br);                     // 3 (profiled)
    csr_scan_kernel<<<1, 1024>>>();                                              // 4
    csr_scatter_kernel<<<(EE + 255) / 256, 256>>>(ei);                           // 5
    edge_enc_kernel<<<EE / 8, 256>>>(ea, eeW, eeb, eeg, eebt);                   // 6

    for (int l = 0; l < LL; l++) {
        if (l > 0)
            lin_kernel<<<lin_grid, 256, LIN_SMEM>>>(Wl + l * DD * DD, bl + l * DD,
                                                    Wr + l * DD * DD, br + l * DD);
        passA_kernel<<<passa_grid, 256, PASSA_SMEM>>>(We + l * EH * DD,
                                                      att + l * HH * CC);
        passB_kernel<<<(NN * 32 + 255) / 256, 256>>>(cb + l * DD, lng + l * DD,
                                                     lnb + l * DD);
    }
    head_kernel<<<NN / 8, 256>>>(out, W1, b1, W2, b2);
}